// round 1
// baseline (speedup 1.0000x reference)
#include <cuda_runtime.h>
#include <cuda_bf16.h>
#include <cstdint>

// Problem constants
// x:     [8, 32, 256, 64]  f32
// baseK: [8, 64, 256, 256] f32  (K = 0..2)
// W:     [64, 224] f32, b: [64] f32
// y:     [8, 64, 256, 64] f32
#define B_   8
#define F_   32
#define C_   256
#define M_   64
#define CO_  64
#define PAIRS 512              // B_*M_
#define KT   32                // K-tile rows of A staged in smem

// Scratch: hop results [blk][pair][f][v], blk = base*2+hop (6 blocks)
__device__ float g_scratch[6 * PAIRS * F_ * C_];   // ~100 MB
// Transposed x: [pair][f][n]
__device__ float g_xT[PAIRS * F_ * C_];            // ~17 MB

// ---------- packed fp32x2 helpers ----------
__device__ __forceinline__ unsigned long long ffma2(unsigned long long a,
                                                    unsigned long long b,
                                                    unsigned long long c) {
    unsigned long long d;
    asm("fma.rn.f32x2 %0, %1, %2, %3;" : "=l"(d) : "l"(a), "l"(b), "l"(c));
    return d;
}
__device__ __forceinline__ unsigned long long dup_f32(float x) {
    unsigned long long r;
    asm("mov.b64 %0, {%1, %1};" : "=l"(r) : "f"(x));
    return r;
}
__device__ __forceinline__ float2 unpack2(unsigned long long v) {
    float2 r;
    asm("mov.b64 {%0, %1}, %2;" : "=f"(r.x), "=f"(r.y) : "l"(v));
    return r;
}

// ---------- kernel 0: transpose x -> xT[pair][f][n] ----------
__global__ void transpose_kernel(const float* __restrict__ x) {
    __shared__ float tile[32][33];
    int bf = blockIdx.z;                 // b*32 + f
    int bb = bf >> 5, f = bf & 31;
    int n0 = blockIdx.x * 32, m0 = blockIdx.y * 32;
    int tx = threadIdx.x, ty = threadIdx.y;   // 32 x 8
    const float* src = x + (size_t)bf * (C_ * M_);   // [n][m]
#pragma unroll
    for (int r = 0; r < 32; r += 8)
        tile[ty + r][tx] = src[(size_t)(n0 + ty + r) * M_ + m0 + tx];
    __syncthreads();
#pragma unroll
    for (int r = 0; r < 32; r += 8) {
        int m = m0 + ty + r, n = n0 + tx;
        g_xT[((size_t)(bb * M_ + m) * F_ + f) * C_ + n] = tile[tx][ty + r];
    }
}

// ---------- kernel 1: hop GEMMs ----------
// One CTA per (pair, base). Computes U = X@A (hop1) and V = U@A (hop2),
// writes both to g_scratch. 128 threads: fg = t/32 (8 f-rows each),
// vg = t%32, v = vg*2 + 64*j (4 float2 column-pairs).
__global__ __launch_bounds__(128, 2)
void hop_kernel(const float* __restrict__ b0,
                const float* __restrict__ b1,
                const float* __restrict__ b2) {
    extern __shared__ float smem[];
    float* Xs = smem;            // 32*256
    float* Us = smem + 8192;     // 32*256
    float* As = smem + 16384;    // KT*256

    int bx = blockIdx.x;         // 0..1535
    int base = bx % 3;
    int pair = bx / 3;           // 0..511
    const float* A = (base == 0 ? b0 : base == 1 ? b1 : b2)
                     + (size_t)pair * (C_ * C_);

    int t  = threadIdx.x;
    int fg = t >> 5;             // 0..3
    int vg = t & 31;

    // load X slice (contiguous, from transposed copy)
    {
        const float4* xsrc = (const float4*)(g_xT + (size_t)pair * (F_ * C_));
        float4* xd = (float4*)Xs;
        for (int i = t; i < F_ * C_ / 4; i += 128) xd[i] = xsrc[i];
    }

    for (int hop = 0; hop < 2; ++hop) {
        const float* src = hop ? Us : Xs;
        unsigned long long acc[8][4];
#pragma unroll
        for (int i = 0; i < 8; ++i)
#pragma unroll
            for (int j = 0; j < 4; ++j) acc[i][j] = 0ULL;

        for (int k0 = 0; k0 < C_; k0 += KT) {
            __syncthreads();   // previous tile compute done (and Xs load on first iter)
            {
                const float4* at = (const float4*)(A + (size_t)k0 * C_);
                float4* ad = (float4*)As;
                for (int i = t; i < KT * C_ / 4; i += 128) ad[i] = at[i];
            }
            __syncthreads();
#pragma unroll 2
            for (int n = 0; n < KT; n += 2) {
                float2 xv[8];
#pragma unroll
                for (int i = 0; i < 8; ++i)
                    xv[i] = *(const float2*)&src[(fg * 8 + i) * C_ + k0 + n];
                unsigned long long a0[4], a1[4];
#pragma unroll
                for (int j = 0; j < 4; ++j) {
                    a0[j] = *(const unsigned long long*)&As[n * C_ + vg * 2 + 64 * j];
                    a1[j] = *(const unsigned long long*)&As[(n + 1) * C_ + vg * 2 + 64 * j];
                }
#pragma unroll
                for (int i = 0; i < 8; ++i) {
                    unsigned long long d0 = dup_f32(xv[i].x);
                    unsigned long long d1 = dup_f32(xv[i].y);
#pragma unroll
                    for (int j = 0; j < 4; ++j) {
                        acc[i][j] = ffma2(d0, a0[j], acc[i][j]);
                        acc[i][j] = ffma2(d1, a1[j], acc[i][j]);
                    }
                }
            }
        }
        // write result
        float* scr = g_scratch + ((size_t)(base * 2 + hop) * PAIRS + pair) * (F_ * C_);
#pragma unroll
        for (int i = 0; i < 8; ++i) {
            int f = fg * 8 + i;
#pragma unroll
            for (int j = 0; j < 4; ++j) {
                int v = vg * 2 + 64 * j;
                float2 val = unpack2(acc[i][j]);
                *(float2*)&scr[f * C_ + v] = val;
                if (hop == 0) *(float2*)&Us[f * C_ + v] = val;
            }
        }
        __syncthreads();   // Us complete before hop 2 reads it
    }
}

// ---------- kernel 2: channel-mixing GEMM + bias ----------
// One CTA per pair. y[b, :, :, m] = W @ h[b, :, :, m] + bias
// h blocks: f 0..31 from xT, f 32.. from g_scratch (6 blocks of 32).
#define WPAD 66   // padded Ws row stride (bank-conflict-free, float2-aligned)
__global__ __launch_bounds__(256, 2)
void mix_kernel(const float* __restrict__ W,
                const float* __restrict__ bias,
                float* __restrict__ y) {
    extern __shared__ float smem[];
    float* Ws = smem;                 // 224 * WPAD
    float* Hs = smem + 224 * WPAD;    // 16 * 256

    int pair = blockIdx.x;            // 0..511
    int bb = pair >> 6, m = pair & 63;
    int t = threadIdx.x;

    // Ws[f*WPAD + o] = W[o*224 + f]  (coalesced global reads)
    for (int i = t; i < CO_ * 224; i += 256) {
        int o = i / 224, f = i % 224;
        Ws[f * WPAD + o] = W[i];
    }

    int og = t >> 5;   // 0..7 -> o = og*8 + i
    int vg = t & 31;   // v = vg*2 + 64*j

    unsigned long long acc[8][4];
#pragma unroll
    for (int i = 0; i < 8; ++i)
#pragma unroll
        for (int j = 0; j < 4; ++j) acc[i][j] = 0ULL;

    for (int ft = 0; ft < 14; ++ft) {
        int f0 = ft * 16;
        const float* src;
        if (f0 < 32) {
            src = g_xT + (size_t)pair * (F_ * C_) + f0 * C_;
        } else {
            int blk = (f0 - 32) >> 5;
            int fr  = (f0 - 32) & 31;
            src = g_scratch + ((size_t)blk * PAIRS + pair) * (F_ * C_) + fr * C_;
        }
        __syncthreads();   // Ws done (first iter) / previous tile compute done
        {
            const float4* s4 = (const float4*)src;
            float4* d4 = (float4*)Hs;
            for (int i = t; i < 16 * C_ / 4; i += 256) d4[i] = s4[i];
        }
        __syncthreads();
#pragma unroll 4
        for (int f = 0; f < 16; ++f) {
            int fa = f0 + f;
            unsigned long long h[4];
#pragma unroll
            for (int j = 0; j < 4; ++j)
                h[j] = *(const unsigned long long*)&Hs[f * C_ + vg * 2 + 64 * j];
#pragma unroll
            for (int i2 = 0; i2 < 4; ++i2) {
                float2 wv = *(const float2*)&Ws[fa * WPAD + og * 8 + 2 * i2];
                unsigned long long w0 = dup_f32(wv.x);
                unsigned long long w1 = dup_f32(wv.y);
#pragma unroll
                for (int j = 0; j < 4; ++j) {
                    acc[2 * i2][j]     = ffma2(w0, h[j], acc[2 * i2][j]);
                    acc[2 * i2 + 1][j] = ffma2(w1, h[j], acc[2 * i2 + 1][j]);
                }
            }
        }
    }

    // write y with bias
#pragma unroll
    for (int i = 0; i < 8; ++i) {
        int o = og * 8 + i;
        float bv = bias[o];
#pragma unroll
        for (int j = 0; j < 4; ++j) {
            int v = vg * 2 + 64 * j;
            float2 r = unpack2(acc[i][j]);
            y[((size_t)(bb * CO_ + o) * C_ + v) * M_ + m]       = r.x + bv;
            y[((size_t)(bb * CO_ + o) * C_ + (v + 1)) * M_ + m] = r.y + bv;
        }
    }
}

extern "C" void kernel_launch(void* const* d_in, const int* in_sizes, int n_in,
                              void* d_out, int out_size) {
    const float* x    = (const float*)d_in[0];
    const float* b0   = (const float*)d_in[1];
    const float* b1   = (const float*)d_in[2];
    const float* b2   = (const float*)d_in[3];
    const float* W    = (const float*)d_in[4];
    const float* bias = (const float*)d_in[5];
    float* y = (float*)d_out;

    cudaFuncSetAttribute(hop_kernel, cudaFuncAttributeMaxDynamicSharedMemorySize,
                         (2 * F_ * C_ + KT * C_) * 4);
    cudaFuncSetAttribute(mix_kernel, cudaFuncAttributeMaxDynamicSharedMemorySize,
                         (224 * WPAD + 16 * C_) * 4);

    transpose_kernel<<<dim3(C_ / 32, M_ / 32, B_ * F_), dim3(32, 8)>>>(x);
    hop_kernel<<<PAIRS * 3, 128, (2 * F_ * C_ + KT * C_) * 4>>>(b0, b1, b2);
    mix_kernel<<<PAIRS, 256, (224 * WPAD + 16 * C_) * 4>>>(W, bias, y);
}

// round 2
// speedup vs baseline: 1.0119x; 1.0119x over previous
#include <cuda_runtime.h>
#include <cuda_bf16.h>
#include <cstdint>

// Problem constants
// x:     [8, 32, 256, 64]  f32
// baseK: [8, 64, 256, 256] f32  (K = 0..2)
// W:     [64, 224] f32, b: [64] f32
// y:     [8, 64, 256, 64] f32
#define B_   8
#define F_   32
#define C_   256
#define M_   64
#define CO_  64
#define PAIRS 512              // B_*M_
#define KT   32                // K-tile rows of A staged in smem

// Scratch: hop results [blk][pair][f][v], blk = base*2+hop (6 blocks)
__device__ float g_scratch[6 * PAIRS * F_ * C_];   // ~100 MB
// Transposed x: [pair][f][n]
__device__ float g_xT[PAIRS * F_ * C_];            // ~17 MB

// ---------- packed fp32x2 helpers ----------
__device__ __forceinline__ unsigned long long ffma2(unsigned long long a,
                                                    unsigned long long b,
                                                    unsigned long long c) {
    unsigned long long d;
    asm("fma.rn.f32x2 %0, %1, %2, %3;" : "=l"(d) : "l"(a), "l"(b), "l"(c));
    return d;
}
__device__ __forceinline__ unsigned long long dup_f32(float x) {
    unsigned long long r;
    asm("mov.b64 %0, {%1, %1};" : "=l"(r) : "f"(x));
    return r;
}
__device__ __forceinline__ float2 unpack2(unsigned long long v) {
    float2 r;
    asm("mov.b64 {%0, %1}, %2;" : "=f"(r.x), "=f"(r.y) : "l"(v));
    return r;
}

// ---------- kernel 0: transpose x -> xT[pair][f][n] ----------
__global__ void transpose_kernel(const float* __restrict__ x) {
    __shared__ float tile[32][33];
    int bf = blockIdx.z;                 // b*32 + f
    int bb = bf >> 5, f = bf & 31;
    int n0 = blockIdx.x * 32, m0 = blockIdx.y * 32;
    int tx = threadIdx.x, ty = threadIdx.y;   // 32 x 8
    const float* src = x + (size_t)bf * (C_ * M_);   // [n][m]
#pragma unroll
    for (int r = 0; r < 32; r += 8)
        tile[ty + r][tx] = src[(size_t)(n0 + ty + r) * M_ + m0 + tx];
    __syncthreads();
#pragma unroll
    for (int r = 0; r < 32; r += 8) {
        int m = m0 + ty + r, n = n0 + tx;
        g_xT[((size_t)(bb * M_ + m) * F_ + f) * C_ + n] = tile[tx][ty + r];
    }
}

// ---------- kernel 1: hop GEMMs ----------
// One CTA per (pair, base). Computes U = X@A (hop1) and V = U@A (hop2),
// writes both to g_scratch. 128 threads: fg = t/32 (8 f-rows each),
// vg = t%32, v = vg*2 + 64*j (4 float2 column-pairs).
__global__ __launch_bounds__(128, 2)
void hop_kernel(const float* __restrict__ b0,
                const float* __restrict__ b1,
                const float* __restrict__ b2) {
    extern __shared__ float smem[];
    float* Xs = smem;            // 32*256
    float* Us = smem + 8192;     // 32*256
    float* As = smem + 16384;    // KT*256

    int bx = blockIdx.x;         // 0..1535
    int base = bx % 3;
    int pair = bx / 3;           // 0..511
    const float* A = (base == 0 ? b0 : base == 1 ? b1 : b2)
                     + (size_t)pair * (C_ * C_);

    int t  = threadIdx.x;
    int fg = t >> 5;             // 0..3
    int vg = t & 31;

    // load X slice (contiguous, from transposed copy)
    {
        const float4* xsrc = (const float4*)(g_xT + (size_t)pair * (F_ * C_));
        float4* xd = (float4*)Xs;
        for (int i = t; i < F_ * C_ / 4; i += 128) xd[i] = xsrc[i];
    }

    for (int hop = 0; hop < 2; ++hop) {
        const float* src = hop ? Us : Xs;
        unsigned long long acc[8][4];
#pragma unroll
        for (int i = 0; i < 8; ++i)
#pragma unroll
            for (int j = 0; j < 4; ++j) acc[i][j] = 0ULL;

        for (int k0 = 0; k0 < C_; k0 += KT) {
            __syncthreads();   // previous tile compute done (and Xs load on first iter)
            {
                const float4* at = (const float4*)(A + (size_t)k0 * C_);
                float4* ad = (float4*)As;
                for (int i = t; i < KT * C_ / 4; i += 128) ad[i] = at[i];
            }
            __syncthreads();
#pragma unroll 2
            for (int n = 0; n < KT; n += 2) {
                float2 xv[8];
#pragma unroll
                for (int i = 0; i < 8; ++i)
                    xv[i] = *(const float2*)&src[(fg * 8 + i) * C_ + k0 + n];
                unsigned long long a0[4], a1[4];
#pragma unroll
                for (int j = 0; j < 4; ++j) {
                    a0[j] = *(const unsigned long long*)&As[n * C_ + vg * 2 + 64 * j];
                    a1[j] = *(const unsigned long long*)&As[(n + 1) * C_ + vg * 2 + 64 * j];
                }
#pragma unroll
                for (int i = 0; i < 8; ++i) {
                    unsigned long long d0 = dup_f32(xv[i].x);
                    unsigned long long d1 = dup_f32(xv[i].y);
#pragma unroll
                    for (int j = 0; j < 4; ++j) {
                        acc[i][j] = ffma2(d0, a0[j], acc[i][j]);
                        acc[i][j] = ffma2(d1, a1[j], acc[i][j]);
                    }
                }
            }
        }
        // write result
        float* scr = g_scratch + ((size_t)(base * 2 + hop) * PAIRS + pair) * (F_ * C_);
#pragma unroll
        for (int i = 0; i < 8; ++i) {
            int f = fg * 8 + i;
#pragma unroll
            for (int j = 0; j < 4; ++j) {
                int v = vg * 2 + 64 * j;
                float2 val = unpack2(acc[i][j]);
                *(float2*)&scr[f * C_ + v] = val;
                if (hop == 0) *(float2*)&Us[f * C_ + v] = val;
            }
        }
        __syncthreads();   // Us complete before hop 2 reads it
    }
}

// ---------- kernel 2: channel-mixing GEMM + bias ----------
// One CTA per pair. y[b, :, :, m] = W @ h[b, :, :, m] + bias
// h blocks: f 0..31 from xT, f 32.. from g_scratch (6 blocks of 32).
#define WPAD 66   // padded Ws row stride (bank-conflict-free, float2-aligned)
__global__ __launch_bounds__(256, 2)
void mix_kernel(const float* __restrict__ W,
                const float* __restrict__ bias,
                float* __restrict__ y) {
    extern __shared__ float smem[];
    float* Ws = smem;                 // 224 * WPAD
    float* Hs = smem + 224 * WPAD;    // 16 * 256

    int pair = blockIdx.x;            // 0..511
    int bb = pair >> 6, m = pair & 63;
    int t = threadIdx.x;

    // Ws[f*WPAD + o] = W[o*224 + f]  (coalesced global reads)
    for (int i = t; i < CO_ * 224; i += 256) {
        int o = i / 224, f = i % 224;
        Ws[f * WPAD + o] = W[i];
    }

    int og = t >> 5;   // 0..7 -> o = og*8 + i
    int vg = t & 31;   // v = vg*2 + 64*j

    unsigned long long acc[8][4];
#pragma unroll
    for (int i = 0; i < 8; ++i)
#pragma unroll
        for (int j = 0; j < 4; ++j) acc[i][j] = 0ULL;

    for (int ft = 0; ft < 14; ++ft) {
        int f0 = ft * 16;
        const float* src;
        if (f0 < 32) {
            src = g_xT + (size_t)pair * (F_ * C_) + f0 * C_;
        } else {
            int blk = (f0 - 32) >> 5;
            int fr  = (f0 - 32) & 31;
            src = g_scratch + ((size_t)blk * PAIRS + pair) * (F_ * C_) + fr * C_;
        }
        __syncthreads();   // Ws done (first iter) / previous tile compute done
        {
            const float4* s4 = (const float4*)src;
            float4* d4 = (float4*)Hs;
            for (int i = t; i < 16 * C_ / 4; i += 256) d4[i] = s4[i];
        }
        __syncthreads();
#pragma unroll 4
        for (int f = 0; f < 16; ++f) {
            int fa = f0 + f;
            unsigned long long h[4];
#pragma unroll
            for (int j = 0; j < 4; ++j)
                h[j] = *(const unsigned long long*)&Hs[f * C_ + vg * 2 + 64 * j];
#pragma unroll
            for (int i2 = 0; i2 < 4; ++i2) {
                float2 wv = *(const float2*)&Ws[fa * WPAD + og * 8 + 2 * i2];
                unsigned long long w0 = dup_f32(wv.x);
                unsigned long long w1 = dup_f32(wv.y);
#pragma unroll
                for (int j = 0; j < 4; ++j) {
                    acc[2 * i2][j]     = ffma2(w0, h[j], acc[2 * i2][j]);
                    acc[2 * i2 + 1][j] = ffma2(w1, h[j], acc[2 * i2 + 1][j]);
                }
            }
        }
    }

    // write y with bias
#pragma unroll
    for (int i = 0; i < 8; ++i) {
        int o = og * 8 + i;
        float bv = bias[o];
#pragma unroll
        for (int j = 0; j < 4; ++j) {
            int v = vg * 2 + 64 * j;
            float2 r = unpack2(acc[i][j]);
            y[((size_t)(bb * CO_ + o) * C_ + v) * M_ + m]       = r.x + bv;
            y[((size_t)(bb * CO_ + o) * C_ + (v + 1)) * M_ + m] = r.y + bv;
        }
    }
}

extern "C" void kernel_launch(void* const* d_in, const int* in_sizes, int n_in,
                              void* d_out, int out_size) {
    const float* x    = (const float*)d_in[0];
    const float* b0   = (const float*)d_in[1];
    const float* b1   = (const float*)d_in[2];
    const float* b2   = (const float*)d_in[3];
    const float* W    = (const float*)d_in[4];
    const float* bias = (const float*)d_in[5];
    float* y = (float*)d_out;

    cudaFuncSetAttribute(hop_kernel, cudaFuncAttributeMaxDynamicSharedMemorySize,
                         (2 * F_ * C_ + KT * C_) * 4);
    cudaFuncSetAttribute(mix_kernel, cudaFuncAttributeMaxDynamicSharedMemorySize,
                         (224 * WPAD + 16 * C_) * 4);

    transpose_kernel<<<dim3(C_ / 32, M_ / 32, B_ * F_), dim3(32, 8)>>>(x);
    hop_kernel<<<PAIRS * 3, 128, (2 * F_ * C_ + KT * C_) * 4>>>(b0, b1, b2);
    mix_kernel<<<PAIRS, 256, (224 * WPAD + 16 * C_) * 4>>>(W, bias, y);
}

// round 5
// speedup vs baseline: 1.6489x; 1.6295x over previous
#include <cuda_runtime.h>
#include <cuda_bf16.h>
#include <cstdint>

// x: [8,32,256,64] f32 | baseK: [8,64,256,256] f32 | W: [64,224] | b: [64] | y: [8,64,256,64]
#define B_   8
#define F_   32
#define C_   256
#define M_   64
#define CO_  64
#define PAIRS 512
#define KC   32              // A chunk rows
#define NCHUNK 8             // 256/KC
#define LDH  264             // padded row stride in bf16 (256+8): 528B = 33*16

__device__ float g_scratch[6 * PAIRS * F_ * C_];
__device__ float g_xT[PAIRS * F_ * C_];

// ---------------- helpers ----------------
__device__ __forceinline__ uint32_t smem_u32(const void* p) {
    uint32_t a;
    asm("{ .reg .u64 t; cvta.to.shared.u64 t, %1; cvt.u32.u64 %0, t; }" : "=r"(a) : "l"(p));
    return a;
}
// bf16 hi/lo split of two floats -> packed bf16x2 (x in low half)
__device__ __forceinline__ void split2(float x, float y, uint32_t& hi, uint32_t& lo) {
    asm("cvt.rn.bf16x2.f32 %0, %1, %2;" : "=r"(hi) : "f"(y), "f"(x));
    float hx = __uint_as_float(hi << 16);
    float hy = __uint_as_float(hi & 0xffff0000u);
    float lx = x - hx, ly = y - hy;
    asm("cvt.rn.bf16x2.f32 %0, %1, %2;" : "=r"(lo) : "f"(ly), "f"(lx));
}
__device__ __forceinline__ void ldm_x4(uint32_t* r, uint32_t addr) {
    asm volatile("ldmatrix.sync.aligned.m8n8.x4.shared.b16 {%0,%1,%2,%3}, [%4];"
                 : "=r"(r[0]), "=r"(r[1]), "=r"(r[2]), "=r"(r[3]) : "r"(addr));
}
__device__ __forceinline__ void ldm_x2t(uint32_t* r, uint32_t addr) {
    asm volatile("ldmatrix.sync.aligned.m8n8.x2.trans.shared.b16 {%0,%1}, [%2];"
                 : "=r"(r[0]), "=r"(r[1]) : "r"(addr));
}
__device__ __forceinline__ void mma_bf16(float* d, const uint32_t* a, const uint32_t* b) {
    asm volatile("mma.sync.aligned.m16n8k16.row.col.f32.bf16.bf16.f32 "
                 "{%0,%1,%2,%3}, {%4,%5,%6,%7}, {%8,%9}, {%0,%1,%2,%3};"
                 : "+f"(d[0]), "+f"(d[1]), "+f"(d[2]), "+f"(d[3])
                 : "r"(a[0]), "r"(a[1]), "r"(a[2]), "r"(a[3]), "r"(b[0]), "r"(b[1]));
}

// ---------------- kernel 0: transpose x -> xT[pair][f][n] ----------------
__global__ void transpose_kernel(const float* __restrict__ x) {
    __shared__ float tile[32][33];
    int bf = blockIdx.z;
    int bb = bf >> 5, f = bf & 31;
    int n0 = blockIdx.x * 32, m0 = blockIdx.y * 32;
    int tx = threadIdx.x, ty = threadIdx.y;
    const float* src = x + (size_t)bf * (C_ * M_);
#pragma unroll
    for (int r = 0; r < 32; r += 8)
        tile[ty + r][tx] = src[(size_t)(n0 + ty + r) * M_ + m0 + tx];
    __syncthreads();
#pragma unroll
    for (int r = 0; r < 32; r += 8) {
        int m = m0 + ty + r, n = n0 + tx;
        g_xT[((size_t)(bb * M_ + m) * F_ + f) * C_ + n] = tile[tx][ty + r];
    }
}

// ---------------- kernel 1: HMMA hop GEMMs ----------------
// smem layout (bf16 units):
//   XsHi [32][LDH] @ 0        XsLo @ 8448
//   AsHi [KC][LDH] @ 16896    AsLo @ 25344
//   staging fp32 (32*LDH floats = 33792B) aliases AsHi..AsLo
__global__ __launch_bounds__(256, 2)
void hop_kernel(const float* __restrict__ b0,
                const float* __restrict__ b1,
                const float* __restrict__ b2) {
    extern __shared__ __align__(16) uint16_t sm[];
    uint16_t* XsHi = sm;
    uint16_t* XsLo = sm + 8448;
    uint16_t* AsHi = sm + 16896;
    uint16_t* AsLo = sm + 25344;
    float*    Stg  = (float*)(sm + 16896);

    int bx = blockIdx.x;
    int base = bx % 3;
    int pair = bx / 3;
    const float* A = (base == 0 ? b0 : base == 1 ? b1 : b2) + (size_t)pair * (C_ * C_);

    int t = threadIdx.x;
    int w = t >> 5;
    int l = t & 31;
    int g = l >> 2;           // group in warp
    int tig = l & 3;
    int mrow = (w >> 2) * 16; // f tile base
    int vbase = (w & 3) * 64; // v slice base

    uint32_t xs_hi_b = smem_u32(XsHi);
    uint32_t xs_lo_b = smem_u32(XsLo);
    uint32_t as_hi_b = smem_u32(AsHi);
    uint32_t as_lo_b = smem_u32(AsLo);

    // ldmatrix lane address components
    int lrow = l & 15;
    int lhalf = (l >> 4) & 1;
    uint32_t x_off = (uint32_t)((mrow + lrow) * LDH + lhalf * 8) * 2;
    uint32_t b_off = (uint32_t)(lrow * LDH + vbase) * 2;

    // ---- initial X -> XsHi/XsLo ----
    {
        const float4* xsrc = (const float4*)(g_xT + (size_t)pair * (F_ * C_));
#pragma unroll
        for (int r = 0; r < 8; ++r) {
            int i = t + 256 * r;              // 2048 float4 total
            int f = i >> 6, q = i & 63;
            float4 v = xsrc[i];
            uint32_t h0, l0, h1, l1;
            split2(v.x, v.y, h0, l0);
            split2(v.z, v.w, h1, l1);
            *(uint2*)&XsHi[f * LDH + q * 4] = make_uint2(h0, h1);
            *(uint2*)&XsLo[f * LDH + q * 4] = make_uint2(l0, l1);
        }
    }

    const float4* A4 = (const float4*)A;

    for (int hop = 0; hop < 2; ++hop) {
        float acc[8][4];
#pragma unroll
        for (int j = 0; j < 8; ++j)
#pragma unroll
            for (int q = 0; q < 4; ++q) acc[j][q] = 0.f;

        // preload chunk 0
        float4 ldg[8];
#pragma unroll
        for (int r = 0; r < 8; ++r) ldg[r] = A4[t + 256 * r];
        // convert + store chunk 0
        __syncthreads();          // staging/scratch copy of prior hop done
#pragma unroll
        for (int r = 0; r < 8; ++r) {
            int i = t + 256 * r;
            int nloc = i >> 6, q = i & 63;
            uint32_t h0, l0, h1, l1;
            split2(ldg[r].x, ldg[r].y, h0, l0);
            split2(ldg[r].z, ldg[r].w, h1, l1);
            *(uint2*)&AsHi[nloc * LDH + q * 4] = make_uint2(h0, h1);
            *(uint2*)&AsLo[nloc * LDH + q * 4] = make_uint2(l0, l1);
        }

        for (int c = 0; c < NCHUNK; ++c) {
            __syncthreads();      // As chunk c visible
            if (c + 1 < NCHUNK) {
#pragma unroll
                for (int r = 0; r < 8; ++r)
                    ldg[r] = A4[(c + 1) * 2048 + t + 256 * r];
            }
#pragma unroll
            for (int ks = 0; ks < 2; ++ks) {
                int k = c * KC + ks * 16;
                uint32_t ah[4], al[4];
                ldm_x4(ah, xs_hi_b + x_off + (uint32_t)k * 2);
                ldm_x4(al, xs_lo_b + x_off + (uint32_t)k * 2);
#pragma unroll
                for (int j = 0; j < 8; ++j) {
                    uint32_t bh[2], bl[2];
                    uint32_t boff = b_off + (uint32_t)(ks * 16 * LDH) * 2 + j * 16;
                    ldm_x2t(bh, as_hi_b + boff);
                    ldm_x2t(bl, as_lo_b + boff);
                    mma_bf16(acc[j], ah, bh);
                    mma_bf16(acc[j], ah, bl);
                    mma_bf16(acc[j], al, bh);
                }
            }
            __syncthreads();      // all warps done reading As chunk c
            if (c + 1 < NCHUNK) {
#pragma unroll
                for (int r = 0; r < 8; ++r) {
                    int i = t + 256 * r;
                    int nloc = i >> 6, q = i & 63;
                    uint32_t h0, l0, h1, l1;
                    split2(ldg[r].x, ldg[r].y, h0, l0);
                    split2(ldg[r].z, ldg[r].w, h1, l1);
                    *(uint2*)&AsHi[nloc * LDH + q * 4] = make_uint2(h0, h1);
                    *(uint2*)&AsLo[nloc * LDH + q * 4] = make_uint2(l0, l1);
                }
            }
        }
        // epilogue: frags -> staging fp32 (+ Us bf16 for hop2). As buffer now free.
#pragma unroll
        for (int j = 0; j < 8; ++j) {
            int col = vbase + 8 * j + 2 * tig;
            int r0 = mrow + g, r1 = mrow + g + 8;
            *(float2*)&Stg[r0 * LDH + col] = make_float2(acc[j][0], acc[j][1]);
            *(float2*)&Stg[r1 * LDH + col] = make_float2(acc[j][2], acc[j][3]);
            if (hop == 0) {
                uint32_t h0, l0, h1, l1;
                split2(acc[j][0], acc[j][1], h0, l0);
                split2(acc[j][2], acc[j][3], h1, l1);
                *(uint32_t*)&XsHi[r0 * LDH + col] = h0;
                *(uint32_t*)&XsLo[r0 * LDH + col] = l0;
                *(uint32_t*)&XsHi[r1 * LDH + col] = h1;
                *(uint32_t*)&XsLo[r1 * LDH + col] = l1;
            }
        }
        __syncthreads();
        // staging -> g_scratch (coalesced)
        {
            float* scr = g_scratch + ((size_t)(base * 2 + hop) * PAIRS + pair) * (F_ * C_);
#pragma unroll
            for (int r = 0; r < 8; ++r) {
                int i = t + 256 * r;
                int f = i >> 6, q = i & 63;
                ((float4*)scr)[i] = *(const float4*)&Stg[f * LDH + q * 4];
            }
        }
        // next hop's first STS waits on __syncthreads at top of its chunk loop
    }
}

// ---------------- kernel 2: channel mix ----------------
__device__ __forceinline__ unsigned long long ffma2(unsigned long long a,
                                                    unsigned long long b,
                                                    unsigned long long c) {
    unsigned long long d;
    asm("fma.rn.f32x2 %0, %1, %2, %3;" : "=l"(d) : "l"(a), "l"(b), "l"(c));
    return d;
}
__device__ __forceinline__ unsigned long long dup_f32(float x) {
    unsigned long long r;
    asm("mov.b64 %0, {%1, %1};" : "=l"(r) : "f"(x));
    return r;
}
__device__ __forceinline__ float2 unpack2(unsigned long long v) {
    float2 r;
    asm("mov.b64 {%0, %1}, %2;" : "=f"(r.x), "=f"(r.y) : "l"(v));
    return r;
}
#define WPAD 66
__global__ __launch_bounds__(256, 2)
void mix_kernel(const float* __restrict__ W,
                const float* __restrict__ bias,
                float* __restrict__ y) {
    extern __shared__ float smemf[];
    float* Ws = smemf;
    float* Hs = smemf + 224 * WPAD;

    int pair = blockIdx.x;
    int bb = pair >> 6, m = pair & 63;
    int t = threadIdx.x;

    for (int i = t; i < CO_ * 224; i += 256) {
        int o = i / 224, f = i % 224;
        Ws[f * WPAD + o] = W[i];
    }

    int og = t >> 5;
    int vg = t & 31;

    unsigned long long acc[8][4];
#pragma unroll
    for (int i = 0; i < 8; ++i)
#pragma unroll
        for (int j = 0; j < 4; ++j) acc[i][j] = 0ULL;

    for (int ft = 0; ft < 14; ++ft) {
        int f0 = ft * 16;
        const float* src;
        if (f0 < 32) {
            src = g_xT + (size_t)pair * (F_ * C_) + f0 * C_;
        } else {
            int blk = (f0 - 32) >> 5;
            int fr  = (f0 - 32) & 31;
            src = g_scratch + ((size_t)blk * PAIRS + pair) * (F_ * C_) + fr * C_;
        }
        __syncthreads();
        {
            const float4* s4 = (const float4*)src;
            float4* d4 = (float4*)Hs;
            for (int i = t; i < 16 * C_ / 4; i += 256) d4[i] = s4[i];
        }
        __syncthreads();
#pragma unroll 4
        for (int f = 0; f < 16; ++f) {
            int fa = f0 + f;
            unsigned long long h[4];
#pragma unroll
            for (int j = 0; j < 4; ++j)
                h[j] = *(const unsigned long long*)&Hs[f * C_ + vg * 2 + 64 * j];
#pragma unroll
            for (int i2 = 0; i2 < 4; ++i2) {
                float2 wv = *(const float2*)&Ws[fa * WPAD + og * 8 + 2 * i2];
                unsigned long long w0 = dup_f32(wv.x);
                unsigned long long w1 = dup_f32(wv.y);
#pragma unroll
                for (int j = 0; j < 4; ++j) {
                    acc[2 * i2][j]     = ffma2(w0, h[j], acc[2 * i2][j]);
                    acc[2 * i2 + 1][j] = ffma2(w1, h[j], acc[2 * i2 + 1][j]);
                }
            }
        }
    }

#pragma unroll
    for (int i = 0; i < 8; ++i) {
        int o = og * 8 + i;
        float bv = bias[o];
#pragma unroll
        for (int j = 0; j < 4; ++j) {
            int v = vg * 2 + 64 * j;
            float2 r = unpack2(acc[i][j]);
            y[((size_t)(bb * CO_ + o) * C_ + v) * M_ + m]       = r.x + bv;
            y[((size_t)(bb * CO_ + o) * C_ + (v + 1)) * M_ + m] = r.y + bv;
        }
    }
}

extern "C" void kernel_launch(void* const* d_in, const int* in_sizes, int n_in,
                              void* d_out, int out_size) {
    const float* x    = (const float*)d_in[0];
    const float* b0   = (const float*)d_in[1];
    const float* b1   = (const float*)d_in[2];
    const float* b2   = (const float*)d_in[3];
    const float* W    = (const float*)d_in[4];
    const float* bias = (const float*)d_in[5];
    float* y = (float*)d_out;

    int hop_smem = 33792 * 2;   // 67584 bytes
    cudaFuncSetAttribute(hop_kernel, cudaFuncAttributeMaxDynamicSharedMemorySize, hop_smem);
    cudaFuncSetAttribute(mix_kernel, cudaFuncAttributeMaxDynamicSharedMemorySize,
                         (224 * WPAD + 16 * C_) * 4);

    transpose_kernel<<<dim3(C_ / 32, M_ / 32, B_ * F_), dim3(32, 8)>>>(x);
    hop_kernel<<<PAIRS * 3, 256, hop_smem>>>(b0, b1, b2);
    mix_kernel<<<PAIRS, 256, (224 * WPAD + 16 * C_) * 4>>>(W, bias, y);
}

// round 6
// speedup vs baseline: 1.7825x; 1.0811x over previous
#include <cuda_runtime.h>
#include <cuda_bf16.h>
#include <cuda_fp16.h>
#include <cstdint>

// x: [8,32,256,64] f32 | baseK: [8,64,256,256] f32 | W: [64,224] | b: [64] | y: [8,64,256,64]
#define B_   8
#define F_   32
#define C_   256
#define M_   64
#define CO_  64
#define PAIRS 512
#define KC   32              // A chunk rows
#define NCHUNK 8             // 256/KC
#define LDH  264             // padded row stride (elements): 528B = 33*16

__device__ float g_scratch[6 * PAIRS * F_ * C_];
__device__ float g_xT[PAIRS * F_ * C_];

// ---------------- helpers ----------------
__device__ __forceinline__ uint32_t smem_u32(const void* p) {
    uint32_t a;
    asm("{ .reg .u64 t; cvta.to.shared.u64 t, %1; cvt.u32.u64 %0, t; }" : "=r"(a) : "l"(p));
    return a;
}
// pack two floats to f16x2 (x -> low half)
__device__ __forceinline__ uint32_t pack_h2(float x, float y) {
    uint32_t r;
    asm("cvt.rn.f16x2.f32 %0, %1, %2;" : "=r"(r) : "f"(y), "f"(x));
    return r;
}
// fp16 hi/lo split of two floats
__device__ __forceinline__ void split2h(float x, float y, uint32_t& hi, uint32_t& lo) {
    hi = pack_h2(x, y);
    float hx, hy;
    asm("{ .reg .f16 a,b; mov.b32 {a,b}, %2; cvt.f32.f16 %0, a; cvt.f32.f16 %1, b; }"
        : "=f"(hx), "=f"(hy) : "r"(hi));
    lo = pack_h2(x - hx, y - hy);
}
__device__ __forceinline__ void ldm_x4(uint32_t* r, uint32_t addr) {
    asm volatile("ldmatrix.sync.aligned.m8n8.x4.shared.b16 {%0,%1,%2,%3}, [%4];"
                 : "=r"(r[0]), "=r"(r[1]), "=r"(r[2]), "=r"(r[3]) : "r"(addr));
}
__device__ __forceinline__ void ldm_x4t(uint32_t* r, uint32_t addr) {
    asm volatile("ldmatrix.sync.aligned.m8n8.x4.trans.shared.b16 {%0,%1,%2,%3}, [%4];"
                 : "=r"(r[0]), "=r"(r[1]), "=r"(r[2]), "=r"(r[3]) : "r"(addr));
}
__device__ __forceinline__ void mma_f16(float* d, const uint32_t* a, const uint32_t* b) {
    asm volatile("mma.sync.aligned.m16n8k16.row.col.f32.f16.f16.f32 "
                 "{%0,%1,%2,%3}, {%4,%5,%6,%7}, {%8,%9}, {%0,%1,%2,%3};"
                 : "+f"(d[0]), "+f"(d[1]), "+f"(d[2]), "+f"(d[3])
                 : "r"(a[0]), "r"(a[1]), "r"(a[2]), "r"(a[3]), "r"(b[0]), "r"(b[1]));
}

// ---------------- kernel 0: transpose x -> xT[pair][f][n] ----------------
__global__ void transpose_kernel(const float* __restrict__ x) {
    __shared__ float tile[32][33];
    int bf = blockIdx.z;
    int bb = bf >> 5, f = bf & 31;
    int n0 = blockIdx.x * 32, m0 = blockIdx.y * 32;
    int tx = threadIdx.x, ty = threadIdx.y;
    const float* src = x + (size_t)bf * (C_ * M_);
#pragma unroll
    for (int r = 0; r < 32; r += 8)
        tile[ty + r][tx] = src[(size_t)(n0 + ty + r) * M_ + m0 + tx];
    __syncthreads();
#pragma unroll
    for (int r = 0; r < 32; r += 8) {
        int m = m0 + ty + r, n = n0 + tx;
        g_xT[((size_t)(bb * M_ + m) * F_ + f) * C_ + n] = tile[tx][ty + r];
    }
}

// ---------------- kernel 1: HMMA hop GEMMs (fp16 2-term) ----------------
// smem (uint16 units):
//   XsHi [32][LDH] @ 0       (16896 B)
//   XsLo [32][LDH] @ 8448    (16896 B)
//   As0  [KC][LDH] @ 16896   (16896 B)   A chunk double buffer (fp16)
//   As1  [KC][LDH] @ 25344   (16896 B)
//   Stg  fp32 [32][LDH] aliases As0+As1 (33792 B)
__global__ __launch_bounds__(256, 2)
void hop_kernel(const float* __restrict__ b0,
                const float* __restrict__ b1,
                const float* __restrict__ b2) {
    extern __shared__ __align__(16) uint16_t sm[];
    uint16_t* XsHi = sm;
    uint16_t* XsLo = sm + 8448;
    uint16_t* As[2] = { sm + 16896, sm + 25344 };
    float*    Stg  = (float*)(sm + 16896);

    int bx = blockIdx.x;
    int base = bx % 3;
    int pair = bx / 3;
    const float* A = (base == 0 ? b0 : base == 1 ? b1 : b2) + (size_t)pair * (C_ * C_);

    int t = threadIdx.x;
    int w = t >> 5;
    int l = t & 31;
    int g = l >> 2;
    int tig = l & 3;
    int mrow = (w >> 2) * 16;   // f tile base (0/16)
    int vbase = (w & 3) * 64;   // v slice base

    uint32_t xs_hi_b = smem_u32(XsHi);
    uint32_t xs_lo_b = smem_u32(XsLo);
    uint32_t as_b[2] = { smem_u32(As[0]), smem_u32(As[1]) };

    // ldmatrix addressing
    int lrow = l & 15;
    int lhalf = (l >> 4) & 1;
    uint32_t x_off = (uint32_t)((mrow + lrow) * LDH + lhalf * 8) * 2;     // A-op (X)
    uint32_t b_off = (uint32_t)(lrow * LDH + vbase + lhalf * 8) * 2;      // B-op x4t

    // ---- initial X -> XsHi/XsLo (fp16 split) ----
    {
        const float4* xsrc = (const float4*)(g_xT + (size_t)pair * (F_ * C_));
#pragma unroll
        for (int r = 0; r < 8; ++r) {
            int i = t + 256 * r;              // 2048 float4
            int f = i >> 6, q = i & 63;
            float4 v = xsrc[i];
            uint32_t h0, l0, h1, l1;
            split2h(v.x, v.y, h0, l0);
            split2h(v.z, v.w, h1, l1);
            *(uint2*)&XsHi[f * LDH + q * 4] = make_uint2(h0, h1);
            *(uint2*)&XsLo[f * LDH + q * 4] = make_uint2(l0, l1);
        }
    }

    const float4* A4 = (const float4*)A;

    for (int hop = 0; hop < 2; ++hop) {
        float acc[8][4];
#pragma unroll
        for (int j = 0; j < 8; ++j)
#pragma unroll
            for (int q = 0; q < 4; ++q) acc[j][q] = 0.f;

        // prologue: chunk 0 -> As[0]
        float4 ldg[8];
#pragma unroll
        for (int r = 0; r < 8; ++r) ldg[r] = A4[t + 256 * r];
        __syncthreads();          // prior-hop readers of Stg alias / X update done
#pragma unroll
        for (int r = 0; r < 8; ++r) {
            int i = t + 256 * r;
            int nloc = i >> 6, q = i & 63;
            uint32_t p0 = pack_h2(ldg[r].x, ldg[r].y);
            uint32_t p1 = pack_h2(ldg[r].z, ldg[r].w);
            *(uint2*)&As[0][nloc * LDH + q * 4] = make_uint2(p0, p1);
        }
        __syncthreads();

        for (int c = 0; c < NCHUNK; ++c) {
            int cur = c & 1, nxt = cur ^ 1;
            if (c + 1 < NCHUNK) {
#pragma unroll
                for (int r = 0; r < 8; ++r)
                    ldg[r] = A4[(c + 1) * 2048 + t + 256 * r];
            }
#pragma unroll
            for (int ks = 0; ks < 2; ++ks) {
                int k = c * KC + ks * 16;
                uint32_t xh[4], xl[4];
                ldm_x4(xh, xs_hi_b + x_off + (uint32_t)k * 2);
                ldm_x4(xl, xs_lo_b + x_off + (uint32_t)k * 2);
                uint32_t bofs = b_off + (uint32_t)(ks * 16 * LDH) * 2;
#pragma unroll
                for (int jj = 0; jj < 4; ++jj) {
                    uint32_t bb4[4];
                    ldm_x4t(bb4, as_b[cur] + bofs + jj * 32);
                    mma_f16(acc[2 * jj],     xh, bb4);
                    mma_f16(acc[2 * jj],     xl, bb4);
                    mma_f16(acc[2 * jj + 1], xh, bb4 + 2);
                    mma_f16(acc[2 * jj + 1], xl, bb4 + 2);
                }
            }
            if (c + 1 < NCHUNK) {
#pragma unroll
                for (int r = 0; r < 8; ++r) {
                    int i = t + 256 * r;
                    int nloc = i >> 6, q = i & 63;
                    uint32_t p0 = pack_h2(ldg[r].x, ldg[r].y);
                    uint32_t p1 = pack_h2(ldg[r].z, ldg[r].w);
                    *(uint2*)&As[nxt][nloc * LDH + q * 4] = make_uint2(p0, p1);
                }
            }
            __syncthreads();      // STS(nxt) visible; all reads of cur done next iter is safe
        }

        // epilogue: frags -> Stg fp32 (+ X update for hop2). As buffers now free.
#pragma unroll
        for (int j = 0; j < 8; ++j) {
            int col = vbase + 8 * j + 2 * tig;
            int r0 = mrow + g, r1 = mrow + g + 8;
            *(float2*)&Stg[r0 * LDH + col] = make_float2(acc[j][0], acc[j][1]);
            *(float2*)&Stg[r1 * LDH + col] = make_float2(acc[j][2], acc[j][3]);
            if (hop == 0) {
                uint32_t h0, l0, h1, l1;
                split2h(acc[j][0], acc[j][1], h0, l0);
                split2h(acc[j][2], acc[j][3], h1, l1);
                *(uint32_t*)&XsHi[r0 * LDH + col] = h0;
                *(uint32_t*)&XsLo[r0 * LDH + col] = l0;
                *(uint32_t*)&XsHi[r1 * LDH + col] = h1;
                *(uint32_t*)&XsLo[r1 * LDH + col] = l1;
            }
        }
        __syncthreads();
        // Stg -> g_scratch (coalesced)
        {
            float* scr = g_scratch + ((size_t)(base * 2 + hop) * PAIRS + pair) * (F_ * C_);
#pragma unroll
            for (int r = 0; r < 8; ++r) {
                int i = t + 256 * r;
                int f = i >> 6, q = i & 63;
                ((float4*)scr)[i] = *(const float4*)&Stg[f * LDH + q * 4];
            }
        }
        // sync at top of next hop's prologue protects Stg alias
    }
}

// ---------------- kernel 2: channel mix ----------------
__device__ __forceinline__ unsigned long long ffma2(unsigned long long a,
                                                    unsigned long long b,
                                                    unsigned long long c) {
    unsigned long long d;
    asm("fma.rn.f32x2 %0, %1, %2, %3;" : "=l"(d) : "l"(a), "l"(b), "l"(c));
    return d;
}
__device__ __forceinline__ unsigned long long dup_f32(float x) {
    unsigned long long r;
    asm("mov.b64 %0, {%1, %1};" : "=l"(r) : "f"(x));
    return r;
}
__device__ __forceinline__ float2 unpack2(unsigned long long v) {
    float2 r;
    asm("mov.b64 {%0, %1}, %2;" : "=f"(r.x), "=f"(r.y) : "l"(v));
    return r;
}
#define WPAD 66
__global__ __launch_bounds__(256, 2)
void mix_kernel(const float* __restrict__ W,
                const float* __restrict__ bias,
                float* __restrict__ y) {
    extern __shared__ float smemf[];
    float* Ws = smemf;
    float* Hs = smemf + 224 * WPAD;

    int pair = blockIdx.x;
    int bb = pair >> 6, m = pair & 63;
    int t = threadIdx.x;

    for (int i = t; i < CO_ * 224; i += 256) {
        int o = i / 224, f = i % 224;
        Ws[f * WPAD + o] = W[i];
    }

    int og = t >> 5;
    int vg = t & 31;

    unsigned long long acc[8][4];
#pragma unroll
    for (int i = 0; i < 8; ++i)
#pragma unroll
        for (int j = 0; j < 4; ++j) acc[i][j] = 0ULL;

    for (int ft = 0; ft < 14; ++ft) {
        int f0 = ft * 16;
        const float* src;
        if (f0 < 32) {
            src = g_xT + (size_t)pair * (F_ * C_) + f0 * C_;
        } else {
            int blk = (f0 - 32) >> 5;
            int fr  = (f0 - 32) & 31;
            src = g_scratch + ((size_t)blk * PAIRS + pair) * (F_ * C_) + fr * C_;
        }
        __syncthreads();
        {
            const float4* s4 = (const float4*)src;
            float4* d4 = (float4*)Hs;
            for (int i = t; i < 16 * C_ / 4; i += 256) d4[i] = s4[i];
        }
        __syncthreads();
#pragma unroll 4
        for (int f = 0; f < 16; ++f) {
            int fa = f0 + f;
            unsigned long long h[4];
#pragma unroll
            for (int j = 0; j < 4; ++j)
                h[j] = *(const unsigned long long*)&Hs[f * C_ + vg * 2 + 64 * j];
#pragma unroll
            for (int i2 = 0; i2 < 4; ++i2) {
                float2 wv = *(const float2*)&Ws[fa * WPAD + og * 8 + 2 * i2];
                unsigned long long w0 = dup_f32(wv.x);
                unsigned long long w1 = dup_f32(wv.y);
#pragma unroll
                for (int j = 0; j < 4; ++j) {
                    acc[2 * i2][j]     = ffma2(w0, h[j], acc[2 * i2][j]);
                    acc[2 * i2 + 1][j] = ffma2(w1, h[j], acc[2 * i2 + 1][j]);
                }
            }
        }
    }

#pragma unroll
    for (int i = 0; i < 8; ++i) {
        int o = og * 8 + i;
        float bv = bias[o];
#pragma unroll
        for (int j = 0; j < 4; ++j) {
            int v = vg * 2 + 64 * j;
            float2 r = unpack2(acc[i][j]);
            y[((size_t)(bb * CO_ + o) * C_ + v) * M_ + m]       = r.x + bv;
            y[((size_t)(bb * CO_ + o) * C_ + (v + 1)) * M_ + m] = r.y + bv;
        }
    }
}

extern "C" void kernel_launch(void* const* d_in, const int* in_sizes, int n_in,
                              void* d_out, int out_size) {
    const float* x    = (const float*)d_in[0];
    const float* b0   = (const float*)d_in[1];
    const float* b1   = (const float*)d_in[2];
    const float* b2   = (const float*)d_in[3];
    const float* W    = (const float*)d_in[4];
    const float* bias = (const float*)d_in[5];
    float* y = (float*)d_out;

    int hop_smem = 67584;
    cudaFuncSetAttribute(hop_kernel, cudaFuncAttributeMaxDynamicSharedMemorySize, hop_smem);
    cudaFuncSetAttribute(mix_kernel, cudaFuncAttributeMaxDynamicSharedMemorySize,
                         (224 * WPAD + 16 * C_) * 4);

    transpose_kernel<<<dim3(C_ / 32, M_ / 32, B_ * F_), dim3(32, 8)>>>(x);
    hop_kernel<<<PAIRS * 3, 256, hop_smem>>>(b0, b1, b2);
    mix_kernel<<<PAIRS, 256, (224 * WPAD + 16 * C_) * 4>>>(W, bias, y);
}

// round 8
// speedup vs baseline: 2.0596x; 1.1554x over previous
#include <cuda_runtime.h>
#include <cuda_bf16.h>
#include <cuda_fp16.h>
#include <cstdint>

// x: [8,32,256,64] f32 | baseK: [8,64,256,256] f32 | W: [64,224] | b: [64] | y: [8,64,256,64]
#define B_   8
#define F_   32
#define C_   256
#define M_   64
#define CO_  64
#define PAIRS 512
#define KC   64              // A chunk rows (hop1 pipeline)
#define NCHUNK 4             // 256/KC
#define LDA  264             // padded row stride (halves): 528B = 33*16

__device__ __half g_scratch_h[6 * PAIRS * F_ * C_];   // hop results, fp16
__device__ float  g_xT[PAIRS * F_ * C_];

// ---------------- helpers ----------------
__device__ __forceinline__ uint32_t smem_u32(const void* p) {
    uint32_t a;
    asm("{ .reg .u64 t; cvta.to.shared.u64 t, %1; cvt.u32.u64 %0, t; }" : "=r"(a) : "l"(p));
    return a;
}
__device__ __forceinline__ uint32_t pack_h2(float x, float y) {
    uint32_t r;
    asm("cvt.rn.f16x2.f32 %0, %1, %2;" : "=r"(r) : "f"(y), "f"(x));
    return r;
}
__device__ __forceinline__ void split2h(float x, float y, uint32_t& hi, uint32_t& lo) {
    hi = pack_h2(x, y);
    float hx, hy;
    asm("{ .reg .f16 a,b; mov.b32 {a,b}, %2; cvt.f32.f16 %0, a; cvt.f32.f16 %1, b; }"
        : "=f"(hx), "=f"(hy) : "r"(hi));
    lo = pack_h2(x - hx, y - hy);
}
__device__ __forceinline__ void ldm_x4(uint32_t* r, uint32_t addr) {
    asm volatile("ldmatrix.sync.aligned.m8n8.x4.shared.b16 {%0,%1,%2,%3}, [%4];"
                 : "=r"(r[0]), "=r"(r[1]), "=r"(r[2]), "=r"(r[3]) : "r"(addr));
}
__device__ __forceinline__ void ldm_x4t(uint32_t* r, uint32_t addr) {
    asm volatile("ldmatrix.sync.aligned.m8n8.x4.trans.shared.b16 {%0,%1,%2,%3}, [%4];"
                 : "=r"(r[0]), "=r"(r[1]), "=r"(r[2]), "=r"(r[3]) : "r"(addr));
}
__device__ __forceinline__ void mma_f16(float* d, const uint32_t* a, const uint32_t* b) {
    asm volatile("mma.sync.aligned.m16n8k16.row.col.f32.f16.f16.f32 "
                 "{%0,%1,%2,%3}, {%4,%5,%6,%7}, {%8,%9}, {%0,%1,%2,%3};"
                 : "+f"(d[0]), "+f"(d[1]), "+f"(d[2]), "+f"(d[3])
                 : "r"(a[0]), "r"(a[1]), "r"(a[2]), "r"(a[3]), "r"(b[0]), "r"(b[1]));
}

// ---------------- kernel 0: transpose x -> xT[pair][f][n] ----------------
__global__ void transpose_kernel(const float* __restrict__ x) {
    __shared__ float tile[32][33];
    int bf = blockIdx.z;
    int bb = bf >> 5, f = bf & 31;
    int n0 = blockIdx.x * 32, m0 = blockIdx.y * 32;
    int tx = threadIdx.x, ty = threadIdx.y;
    const float* src = x + (size_t)bf * (C_ * M_);
#pragma unroll
    for (int r = 0; r < 32; r += 8)
        tile[ty + r][tx] = src[(size_t)(n0 + ty + r) * M_ + m0 + tx];
    __syncthreads();
#pragma unroll
    for (int r = 0; r < 32; r += 8) {
        int m = m0 + ty + r, n = n0 + tx;
        g_xT[((size_t)(bb * M_ + m) * F_ + f) * C_ + n] = tile[tx][ty + r];
    }
}

// ---------------- kernel 1: HMMA hop GEMMs, persistent fp16 A ----------------
// smem (halves):
//   As   [256][LDA] @ 0          (135168 B) persistent fp16 A
//   XsHi [32][LDA]  @ 67584      (16896 B)
//   XsLo [32][LDA]  @ 76032      (16896 B)
//   StgH [32][LDA]  @ 84480      (16896 B) fp16 result staging
// total 185856 B, occ = 1 CTA (512 thr)
__global__ __launch_bounds__(512, 1)
void hop_kernel(const float* __restrict__ b0,
                const float* __restrict__ b1,
                const float* __restrict__ b2) {
    extern __shared__ __align__(16) uint16_t sm[];
    uint16_t* As   = sm;
    uint16_t* XsHi = sm + 67584;
    uint16_t* XsLo = sm + 76032;
    uint16_t* StgH = sm + 84480;

    int bx = blockIdx.x;
    int base = bx % 3;
    int pair = bx / 3;
    const float* A = (base == 0 ? b0 : base == 1 ? b1 : b2) + (size_t)pair * (C_ * C_);

    int t = threadIdx.x;
    int w = t >> 5;
    int l = t & 31;
    int g = l >> 2;
    int tig = l & 3;
    int mrow  = (w >> 3) * 16;   // f tile base (0/16)
    int vbase = (w & 7) * 32;    // v slice base (32 wide)

    uint32_t xs_hi_b = smem_u32(XsHi);
    uint32_t xs_lo_b = smem_u32(XsLo);
    uint32_t as_b    = smem_u32(As);

    int lrow = l & 15;
    int lhalf = (l >> 4) & 1;
    uint32_t x_off = (uint32_t)((mrow + lrow) * LDA + lhalf * 8) * 2;
    uint32_t b_off = (uint32_t)(lrow * LDA + vbase + lhalf * 8) * 2;

    // ---- initial X -> XsHi/XsLo (fp16 split) ----
    {
        const float4* xsrc = (const float4*)(g_xT + (size_t)pair * (F_ * C_));
#pragma unroll
        for (int r = 0; r < 4; ++r) {
            int i = t + 512 * r;              // 2048 float4
            int f = i >> 6, q = i & 63;
            float4 v = xsrc[i];
            uint32_t h0, l0, h1, l1;
            split2h(v.x, v.y, h0, l0);
            split2h(v.z, v.w, h1, l1);
            *(uint2*)&XsHi[f * LDA + q * 4] = make_uint2(h0, h1);
            *(uint2*)&XsLo[f * LDA + q * 4] = make_uint2(l0, l1);
        }
    }

    const float4* A4 = (const float4*)A;
    float acc[4][4];

    // ================= hop 0: stream A chunks (fill As), MMA =================
#pragma unroll
    for (int j = 0; j < 4; ++j)
#pragma unroll
        for (int q = 0; q < 4; ++q) acc[j][q] = 0.f;

    float4 ldg[8];
#pragma unroll
    for (int r = 0; r < 8; ++r) ldg[r] = A4[t + 512 * r];   // chunk 0 (64 rows)
#pragma unroll
    for (int r = 0; r < 8; ++r) {
        int i = t + 512 * r;
        int nloc = i >> 6, q = i & 63;
        uint32_t p0 = pack_h2(ldg[r].x, ldg[r].y);
        uint32_t p1 = pack_h2(ldg[r].z, ldg[r].w);
        *(uint2*)&As[nloc * LDA + q * 4] = make_uint2(p0, p1);
    }
    __syncthreads();

    for (int c = 0; c < NCHUNK; ++c) {
        if (c + 1 < NCHUNK) {
#pragma unroll
            for (int r = 0; r < 8; ++r)
                ldg[r] = A4[(c + 1) * 4096 + t + 512 * r];
        }
#pragma unroll
        for (int ks = 0; ks < 4; ++ks) {
            int k = c * KC + ks * 16;
            uint32_t xh[4], xl[4];
            ldm_x4(xh, xs_hi_b + x_off + (uint32_t)k * 2);
            ldm_x4(xl, xs_lo_b + x_off + (uint32_t)k * 2);
            uint32_t rofs = b_off + (uint32_t)(k * LDA) * 2;
#pragma unroll
            for (int jj = 0; jj < 2; ++jj) {
                uint32_t bb4[4];
                ldm_x4t(bb4, as_b + rofs + jj * 32);
                mma_f16(acc[2 * jj],     xh, bb4);
                mma_f16(acc[2 * jj],     xl, bb4);
                mma_f16(acc[2 * jj + 1], xh, bb4 + 2);
                mma_f16(acc[2 * jj + 1], xl, bb4 + 2);
            }
        }
        if (c + 1 < NCHUNK) {
            int rb = (c + 1) * KC;
#pragma unroll
            for (int r = 0; r < 8; ++r) {
                int i = t + 512 * r;
                int nloc = i >> 6, q = i & 63;
                uint32_t p0 = pack_h2(ldg[r].x, ldg[r].y);
                uint32_t p1 = pack_h2(ldg[r].z, ldg[r].w);
                *(uint2*)&As[(rb + nloc) * LDA + q * 4] = make_uint2(p0, p1);
            }
        }
        __syncthreads();
    }

    // epilogue hop 0: StgH fp16 + X update
#pragma unroll
    for (int j = 0; j < 4; ++j) {
        int col = vbase + 8 * j + 2 * tig;
        int r0 = mrow + g, r1 = mrow + g + 8;
        *(uint32_t*)&StgH[r0 * LDA + col] = pack_h2(acc[j][0], acc[j][1]);
        *(uint32_t*)&StgH[r1 * LDA + col] = pack_h2(acc[j][2], acc[j][3]);
        uint32_t h0, l0, h1, l1;
        split2h(acc[j][0], acc[j][1], h0, l0);
        split2h(acc[j][2], acc[j][3], h1, l1);
        *(uint32_t*)&XsHi[r0 * LDA + col] = h0;
        *(uint32_t*)&XsLo[r0 * LDA + col] = l0;
        *(uint32_t*)&XsHi[r1 * LDA + col] = h1;
        *(uint32_t*)&XsLo[r1 * LDA + col] = l1;
    }
    __syncthreads();
    // copy StgH -> scratch (coalesced, 1024 uint4)
    {
        __half* scr = g_scratch_h + ((size_t)(base * 2 + 0) * PAIRS + pair) * (F_ * C_);
#pragma unroll
        for (int r = 0; r < 2; ++r) {
            int i = t + 512 * r;
            int f = i >> 5, q = i & 31;
            ((uint4*)scr)[i] = *(const uint4*)&StgH[f * LDA + q * 8];
        }
    }
    __syncthreads();   // StgH free + X update visible before hop 1

    // ================= hop 1: all from smem =================
#pragma unroll
    for (int j = 0; j < 4; ++j)
#pragma unroll
        for (int q = 0; q < 4; ++q) acc[j][q] = 0.f;

#pragma unroll 4
    for (int ks = 0; ks < 16; ++ks) {
        int k = ks * 16;
        uint32_t xh[4], xl[4];
        ldm_x4(xh, xs_hi_b + x_off + (uint32_t)k * 2);
        ldm_x4(xl, xs_lo_b + x_off + (uint32_t)k * 2);
        uint32_t rofs = b_off + (uint32_t)(k * LDA) * 2;
#pragma unroll
        for (int jj = 0; jj < 2; ++jj) {
            uint32_t bb4[4];
            ldm_x4t(bb4, as_b + rofs + jj * 32);
            mma_f16(acc[2 * jj],     xh, bb4);
            mma_f16(acc[2 * jj],     xl, bb4);
            mma_f16(acc[2 * jj + 1], xh, bb4 + 2);
            mma_f16(acc[2 * jj + 1], xl, bb4 + 2);
        }
    }
#pragma unroll
    for (int j = 0; j < 4; ++j) {
        int col = vbase + 8 * j + 2 * tig;
        int r0 = mrow + g, r1 = mrow + g + 8;
        *(uint32_t*)&StgH[r0 * LDA + col] = pack_h2(acc[j][0], acc[j][1]);
        *(uint32_t*)&StgH[r1 * LDA + col] = pack_h2(acc[j][2], acc[j][3]);
    }
    __syncthreads();
    {
        __half* scr = g_scratch_h + ((size_t)(base * 2 + 1) * PAIRS + pair) * (F_ * C_);
#pragma unroll
        for (int r = 0; r < 2; ++r) {
            int i = t + 512 * r;
            int f = i >> 5, q = i & 31;
            ((uint4*)scr)[i] = *(const uint4*)&StgH[f * LDA + q * 8];
        }
    }
}

// ---------------- kernel 2: channel mix ----------------
__device__ __forceinline__ unsigned long long ffma2(unsigned long long a,
                                                    unsigned long long b,
                                                    unsigned long long c) {
    unsigned long long d;
    asm("fma.rn.f32x2 %0, %1, %2, %3;" : "=l"(d) : "l"(a), "l"(b), "l"(c));
    return d;
}
__device__ __forceinline__ unsigned long long dup_f32(float x) {
    unsigned long long r;
    asm("mov.b64 %0, {%1, %1};" : "=l"(r) : "f"(x));
    return r;
}
__device__ __forceinline__ float2 unpack2(unsigned long long v) {
    float2 r;
    asm("mov.b64 {%0, %1}, %2;" : "=f"(r.x), "=f"(r.y) : "l"(v));
    return r;
}
#define WPAD 66
__global__ __launch_bounds__(256, 2)
void mix_kernel(const float* __restrict__ W,
                const float* __restrict__ bias,
                float* __restrict__ y) {
    extern __shared__ float smemf[];
    float* Ws = smemf;
    float* Hs = smemf + 224 * WPAD;

    int pair = blockIdx.x;
    int bb = pair >> 6, m = pair & 63;
    int t = threadIdx.x;

    for (int i = t; i < CO_ * 224; i += 256) {
        int o = i / 224, f = i % 224;
        Ws[f * WPAD + o] = W[i];
    }

    int og = t >> 5;
    int vg = t & 31;

    unsigned long long acc[8][4];
#pragma unroll
    for (int i = 0; i < 8; ++i)
#pragma unroll
        for (int j = 0; j < 4; ++j) acc[i][j] = 0ULL;

    for (int ft = 0; ft < 14; ++ft) {
        int f0 = ft * 16;
        __syncthreads();
        if (f0 < 32) {
            const float4* s4 = (const float4*)(g_xT + (size_t)pair * (F_ * C_) + f0 * C_);
            float4* d4 = (float4*)Hs;
            for (int i = t; i < 16 * C_ / 4; i += 256) d4[i] = s4[i];
        } else {
            int blk = (f0 - 32) >> 5;
            int fr  = (f0 - 32) & 31;
            const __half* srch = g_scratch_h + ((size_t)blk * PAIRS + pair) * (F_ * C_) + fr * C_;
            const uint4* s4 = (const uint4*)srch;
#pragma unroll
            for (int r = 0; r < 2; ++r) {
                int i = t + 256 * r;          // 512 uint4 (8 halves each)
                uint4 u = s4[i];
                float2 f0v = __half22float2(*(__half2*)&u.x);
                float2 f1v = __half22float2(*(__half2*)&u.y);
                float2 f2v = __half22float2(*(__half2*)&u.z);
                float2 f3v = __half22float2(*(__half2*)&u.w);
                float* d = &Hs[(i >> 5) * C_ + (i & 31) * 8];
                *(float4*)d       = make_float4(f0v.x, f0v.y, f1v.x, f1v.y);
                *(float4*)(d + 4) = make_float4(f2v.x, f2v.y, f3v.x, f3v.y);
            }
        }
        __syncthreads();
#pragma unroll 4
        for (int f = 0; f < 16; ++f) {
            int fa = f0 + f;
            unsigned long long h[4];
#pragma unroll
            for (int j = 0; j < 4; ++j)
                h[j] = *(const unsigned long long*)&Hs[f * C_ + vg * 2 + 64 * j];
#pragma unroll
            for (int i2 = 0; i2 < 4; ++i2) {
                float2 wv = *(const float2*)&Ws[fa * WPAD + og * 8 + 2 * i2];
                unsigned long long w0 = dup_f32(wv.x);
                unsigned long long w1 = dup_f32(wv.y);
#pragma unroll
                for (int j = 0; j < 4; ++j) {
                    acc[2 * i2][j]     = ffma2(w0, h[j], acc[2 * i2][j]);
                    acc[2 * i2 + 1][j] = ffma2(w1, h[j], acc[2 * i2 + 1][j]);
                }
            }
        }
    }

#pragma unroll
    for (int i = 0; i < 8; ++i) {
        int o = og * 8 + i;
        float bv = bias[o];
#pragma unroll
        for (int j = 0; j < 4; ++j) {
            int v = vg * 2 + 64 * j;
            float2 r = unpack2(acc[i][j]);
            y[((size_t)(bb * CO_ + o) * C_ + v) * M_ + m]       = r.x + bv;
            y[((size_t)(bb * CO_ + o) * C_ + (v + 1)) * M_ + m] = r.y + bv;
        }
    }
}

extern "C" void kernel_launch(void* const* d_in, const int* in_sizes, int n_in,
                              void* d_out, int out_size) {
    const float* x    = (const float*)d_in[0];
    const float* b0   = (const float*)d_in[1];
    const float* b1   = (const float*)d_in[2];
    const float* b2   = (const float*)d_in[3];
    const float* W    = (const float*)d_in[4];
    const float* bias = (const float*)d_in[5];
    float* y = (float*)d_out;

    int hop_smem = 185856;
    cudaFuncSetAttribute(hop_kernel, cudaFuncAttributeMaxDynamicSharedMemorySize, hop_smem);
    cudaFuncSetAttribute(mix_kernel, cudaFuncAttributeMaxDynamicSharedMemorySize,
                         (224 * WPAD + 16 * C_) * 4);

    transpose_kernel<<<dim3(C_ / 32, M_ / 32, B_ * F_), dim3(32, 8)>>>(x);
    hop_kernel<<<PAIRS * 3, 512, hop_smem>>>(b0, b1, b2);
    mix_kernel<<<PAIRS, 256, (224 * WPAD + 16 * C_) * 4>>>(W, bias, y);
}

// round 10
// speedup vs baseline: 2.1641x; 1.0507x over previous
#include <cuda_runtime.h>
#include <cuda_bf16.h>
#include <cuda_fp16.h>
#include <cstdint>

// x: [8,32,256,64] f32 | baseK: [8,64,256,256] f32 | W: [64,224] | b: [64] | y: [8,64,256,64]
#define B_   8
#define F_   32
#define C_   256
#define M_   64
#define CO_  64
#define PAIRS 512
#define KC   64              // A chunk rows (hop0 pipeline)
#define NCHUNK 4             // 256/KC
#define LDA  264             // padded row stride (halves): 528B = 33*16

__device__ __half g_scratch_h[6 * PAIRS * F_ * C_];   // hop results, fp16
__device__ float  g_xT[PAIRS * F_ * C_];

// ---------------- helpers ----------------
__device__ __forceinline__ uint32_t smem_u32(const void* p) {
    uint32_t a;
    asm("{ .reg .u64 t; cvta.to.shared.u64 t, %1; cvt.u32.u64 %0, t; }" : "=r"(a) : "l"(p));
    return a;
}
__device__ __forceinline__ uint32_t pack_h2(float x, float y) {
    uint32_t r;
    asm("cvt.rn.f16x2.f32 %0, %1, %2;" : "=r"(r) : "f"(y), "f"(x));
    return r;
}
__device__ __forceinline__ void ldm_x4(uint32_t* r, uint32_t addr) {
    asm volatile("ldmatrix.sync.aligned.m8n8.x4.shared.b16 {%0,%1,%2,%3}, [%4];"
                 : "=r"(r[0]), "=r"(r[1]), "=r"(r[2]), "=r"(r[3]) : "r"(addr));
}
__device__ __forceinline__ void ldm_x4t(uint32_t* r, uint32_t addr) {
    asm volatile("ldmatrix.sync.aligned.m8n8.x4.trans.shared.b16 {%0,%1,%2,%3}, [%4];"
                 : "=r"(r[0]), "=r"(r[1]), "=r"(r[2]), "=r"(r[3]) : "r"(addr));
}
__device__ __forceinline__ void mma_f16(float* d, const uint32_t* a, const uint32_t* b) {
    asm volatile("mma.sync.aligned.m16n8k16.row.col.f32.f16.f16.f32 "
                 "{%0,%1,%2,%3}, {%4,%5,%6,%7}, {%8,%9}, {%0,%1,%2,%3};"
                 : "+f"(d[0]), "+f"(d[1]), "+f"(d[2]), "+f"(d[3])
                 : "r"(a[0]), "r"(a[1]), "r"(a[2]), "r"(a[3]), "r"(b[0]), "r"(b[1]));
}

// ---------------- kernel 0: transpose x -> xT[pair][f][n] ----------------
__global__ void transpose_kernel(const float* __restrict__ x) {
    __shared__ float tile[32][33];
    int bf = blockIdx.z;
    int bb = bf >> 5, f = bf & 31;
    int n0 = blockIdx.x * 32, m0 = blockIdx.y * 32;
    int tx = threadIdx.x, ty = threadIdx.y;
    const float* src = x + (size_t)bf * (C_ * M_);
#pragma unroll
    for (int r = 0; r < 32; r += 8)
        tile[ty + r][tx] = src[(size_t)(n0 + ty + r) * M_ + m0 + tx];
    __syncthreads();
#pragma unroll
    for (int r = 0; r < 32; r += 8) {
        int m = m0 + ty + r, n = n0 + tx;
        g_xT[((size_t)(bb * M_ + m) * F_ + f) * C_ + n] = tile[tx][ty + r];
    }
}

// ---------------- kernel 1: HMMA hop GEMMs, single fp16, persistent A ----------------
// smem (halves):
//   As   [256][LDA] @ 0        (67584 halves, 135168 B) persistent fp16 A
//   Xs   [32][LDA]  @ 67584    (8448 halves)
//   StgH [32][LDA]  @ 76032    (8448 halves) fp16 result staging
// total 84480 halves = 168960 B, occ = 1 CTA (512 thr)
__global__ __launch_bounds__(512, 1)
void hop_kernel(const float* __restrict__ b0,
                const float* __restrict__ b1,
                const float* __restrict__ b2) {
    extern __shared__ __align__(16) uint16_t sm[];
    uint16_t* As   = sm;
    uint16_t* Xs   = sm + 67584;
    uint16_t* StgH = sm + 76032;

    int bx = blockIdx.x;
    int base = bx % 3;
    int pair = bx / 3;
    const float* A = (base == 0 ? b0 : base == 1 ? b1 : b2) + (size_t)pair * (C_ * C_);

    int t = threadIdx.x;
    int w = t >> 5;
    int l = t & 31;
    int g = l >> 2;
    int tig = l & 3;
    int mrow  = (w >> 3) * 16;   // f tile base (0/16)
    int vbase = (w & 7) * 32;    // v slice base (32 wide)

    uint32_t xs_b = smem_u32(Xs);
    uint32_t as_b = smem_u32(As);

    int lrow = l & 15;
    int lhalf = (l >> 4) & 1;
    uint32_t x_off = (uint32_t)((mrow + lrow) * LDA + lhalf * 8) * 2;
    uint32_t b_off = (uint32_t)(lrow * LDA + vbase + lhalf * 8) * 2;

    // ---- initial X -> Xs (single fp16) ----
    {
        const float4* xsrc = (const float4*)(g_xT + (size_t)pair * (F_ * C_));
#pragma unroll
        for (int r = 0; r < 4; ++r) {
            int i = t + 512 * r;              // 2048 float4
            int f = i >> 6, q = i & 63;
            float4 v = xsrc[i];
            uint32_t p0 = pack_h2(v.x, v.y);
            uint32_t p1 = pack_h2(v.z, v.w);
            *(uint2*)&Xs[f * LDA + q * 4] = make_uint2(p0, p1);
        }
    }

    const float4* A4 = (const float4*)A;
    float acc[4][4];

    // ================= hop 0: stream A chunks (fill As), MMA =================
#pragma unroll
    for (int j = 0; j < 4; ++j)
#pragma unroll
        for (int q = 0; q < 4; ++q) acc[j][q] = 0.f;

    float4 ldg[8];
#pragma unroll
    for (int r = 0; r < 8; ++r) ldg[r] = A4[t + 512 * r];   // chunk 0 (64 rows)
#pragma unroll
    for (int r = 0; r < 8; ++r) {
        int i = t + 512 * r;
        int nloc = i >> 6, q = i & 63;
        uint32_t p0 = pack_h2(ldg[r].x, ldg[r].y);
        uint32_t p1 = pack_h2(ldg[r].z, ldg[r].w);
        *(uint2*)&As[nloc * LDA + q * 4] = make_uint2(p0, p1);
    }
    __syncthreads();

    for (int c = 0; c < NCHUNK; ++c) {
        if (c + 1 < NCHUNK) {
#pragma unroll
            for (int r = 0; r < 8; ++r)
                ldg[r] = A4[(c + 1) * 4096 + t + 512 * r];
        }
#pragma unroll
        for (int ks = 0; ks < 4; ++ks) {
            int k = c * KC + ks * 16;
            uint32_t xh[4];
            ldm_x4(xh, xs_b + x_off + (uint32_t)k * 2);
            uint32_t rofs = b_off + (uint32_t)(k * LDA) * 2;
#pragma unroll
            for (int jj = 0; jj < 2; ++jj) {
                uint32_t bb4[4];
                ldm_x4t(bb4, as_b + rofs + jj * 32);
                mma_f16(acc[2 * jj],     xh, bb4);
                mma_f16(acc[2 * jj + 1], xh, bb4 + 2);
            }
        }
        if (c + 1 < NCHUNK) {
            int rb = (c + 1) * KC;
#pragma unroll
            for (int r = 0; r < 8; ++r) {
                int i = t + 512 * r;
                int nloc = i >> 6, q = i & 63;
                uint32_t p0 = pack_h2(ldg[r].x, ldg[r].y);
                uint32_t p1 = pack_h2(ldg[r].z, ldg[r].w);
                *(uint2*)&As[(rb + nloc) * LDA + q * 4] = make_uint2(p0, p1);
            }
        }
        __syncthreads();
    }

    // epilogue hop 0: StgH fp16 + X update (single fp16)
#pragma unroll
    for (int j = 0; j < 4; ++j) {
        int col = vbase + 8 * j + 2 * tig;
        int r0 = mrow + g, r1 = mrow + g + 8;
        uint32_t p0 = pack_h2(acc[j][0], acc[j][1]);
        uint32_t p1 = pack_h2(acc[j][2], acc[j][3]);
        *(uint32_t*)&StgH[r0 * LDA + col] = p0;
        *(uint32_t*)&StgH[r1 * LDA + col] = p1;
        *(uint32_t*)&Xs[r0 * LDA + col] = p0;
        *(uint32_t*)&Xs[r1 * LDA + col] = p1;
    }
    __syncthreads();
    // StgH -> scratch (coalesced, 1024 uint4)
    {
        __half* scr = g_scratch_h + ((size_t)(base * 2 + 0) * PAIRS + pair) * (F_ * C_);
#pragma unroll
        for (int r = 0; r < 2; ++r) {
            int i = t + 512 * r;
            int f = i >> 5, q = i & 31;
            ((uint4*)scr)[i] = *(const uint4*)&StgH[f * LDA + q * 8];
        }
    }
    __syncthreads();   // StgH free + X update visible before hop 1

    // ================= hop 1: all from smem =================
#pragma unroll
    for (int j = 0; j < 4; ++j)
#pragma unroll
        for (int q = 0; q < 4; ++q) acc[j][q] = 0.f;

#pragma unroll 4
    for (int ks = 0; ks < 16; ++ks) {
        int k = ks * 16;
        uint32_t xh[4];
        ldm_x4(xh, xs_b + x_off + (uint32_t)k * 2);
        uint32_t rofs = b_off + (uint32_t)(k * LDA) * 2;
#pragma unroll
        for (int jj = 0; jj < 2; ++jj) {
            uint32_t bb4[4];
            ldm_x4t(bb4, as_b + rofs + jj * 32);
            mma_f16(acc[2 * jj],     xh, bb4);
            mma_f16(acc[2 * jj + 1], xh, bb4 + 2);
        }
    }
#pragma unroll
    for (int j = 0; j < 4; ++j) {
        int col = vbase + 8 * j + 2 * tig;
        int r0 = mrow + g, r1 = mrow + g + 8;
        *(uint32_t*)&StgH[r0 * LDA + col] = pack_h2(acc[j][0], acc[j][1]);
        *(uint32_t*)&StgH[r1 * LDA + col] = pack_h2(acc[j][2], acc[j][3]);
    }
    __syncthreads();
    {
        __half* scr = g_scratch_h + ((size_t)(base * 2 + 1) * PAIRS + pair) * (F_ * C_);
#pragma unroll
        for (int r = 0; r < 2; ++r) {
            int i = t + 512 * r;
            int f = i >> 5, q = i & 31;
            ((uint4*)scr)[i] = *(const uint4*)&StgH[f * LDA + q * 8];
        }
    }
}

// ---------------- kernel 2: channel mix ----------------
__device__ __forceinline__ unsigned long long ffma2(unsigned long long a,
                                                    unsigned long long b,
                                                    unsigned long long c) {
    unsigned long long d;
    asm("fma.rn.f32x2 %0, %1, %2, %3;" : "=l"(d) : "l"(a), "l"(b), "l"(c));
    return d;
}
__device__ __forceinline__ unsigned long long dup_f32(float x) {
    unsigned long long r;
    asm("mov.b64 %0, {%1, %1};" : "=l"(r) : "f"(x));
    return r;
}
__device__ __forceinline__ float2 unpack2(unsigned long long v) {
    float2 r;
    asm("mov.b64 {%0, %1}, %2;" : "=f"(r.x), "=f"(r.y) : "l"(v));
    return r;
}
#define WPAD 66
__global__ __launch_bounds__(256, 2)
void mix_kernel(const float* __restrict__ W,
                const float* __restrict__ bias,
                float* __restrict__ y) {
    extern __shared__ float smemf[];
    float* Ws = smemf;
    float* Hs = smemf + 224 * WPAD;

    int pair = blockIdx.x;
    int bb = pair >> 6, m = pair & 63;
    int t = threadIdx.x;

    for (int i = t; i < CO_ * 224; i += 256) {
        int o = i / 224, f = i % 224;
        Ws[f * WPAD + o] = W[i];
    }

    int og = t >> 5;
    int vg = t & 31;

    unsigned long long acc[8][4];
#pragma unroll
    for (int i = 0; i < 8; ++i)
#pragma unroll
        for (int j = 0; j < 4; ++j) acc[i][j] = 0ULL;

    for (int ft = 0; ft < 14; ++ft) {
        int f0 = ft * 16;
        __syncthreads();
        if (f0 < 32) {
            const float4* s4 = (const float4*)(g_xT + (size_t)pair * (F_ * C_) + f0 * C_);
            float4* d4 = (float4*)Hs;
            for (int i = t; i < 16 * C_ / 4; i += 256) d4[i] = s4[i];
        } else {
            int blk = (f0 - 32) >> 5;
            int fr  = (f0 - 32) & 31;
            const __half* srch = g_scratch_h + ((size_t)blk * PAIRS + pair) * (F_ * C_) + fr * C_;
            const uint4* s4 = (const uint4*)srch;
#pragma unroll
            for (int r = 0; r < 2; ++r) {
                int i = t + 256 * r;          // 512 uint4 (8 halves each)
                uint4 u = s4[i];
                float2 f0v = __half22float2(*(__half2*)&u.x);
                float2 f1v = __half22float2(*(__half2*)&u.y);
                float2 f2v = __half22float2(*(__half2*)&u.z);
                float2 f3v = __half22float2(*(__half2*)&u.w);
                float* d = &Hs[(i >> 5) * C_ + (i & 31) * 8];
                *(float4*)d       = make_float4(f0v.x, f0v.y, f1v.x, f1v.y);
                *(float4*)(d + 4) = make_float4(f2v.x, f2v.y, f3v.x, f3v.y);
            }
        }
        __syncthreads();
#pragma unroll 4
        for (int f = 0; f < 16; ++f) {
            int fa = f0 + f;
            unsigned long long h[4];
#pragma unroll
            for (int j = 0; j < 4; ++j)
                h[j] = *(const unsigned long long*)&Hs[f * C_ + vg * 2 + 64 * j];
#pragma unroll
            for (int i2 = 0; i2 < 4; ++i2) {
                float2 wv = *(const float2*)&Ws[fa * WPAD + og * 8 + 2 * i2];
                unsigned long long w0 = dup_f32(wv.x);
                unsigned long long w1 = dup_f32(wv.y);
#pragma unroll
                for (int j = 0; j < 4; ++j) {
                    acc[2 * i2][j]     = ffma2(w0, h[j], acc[2 * i2][j]);
                    acc[2 * i2 + 1][j] = ffma2(w1, h[j], acc[2 * i2 + 1][j]);
                }
            }
        }
    }

#pragma unroll
    for (int i = 0; i < 8; ++i) {
        int o = og * 8 + i;
        float bv = bias[o];
#pragma unroll
        for (int j = 0; j < 4; ++j) {
            int v = vg * 2 + 64 * j;
            float2 r = unpack2(acc[i][j]);
            y[((size_t)(bb * CO_ + o) * C_ + v) * M_ + m]       = r.x + bv;
            y[((size_t)(bb * CO_ + o) * C_ + (v + 1)) * M_ + m] = r.y + bv;
        }
    }
}

extern "C" void kernel_launch(void* const* d_in, const int* in_sizes, int n_in,
                              void* d_out, int out_size) {
    const float* x    = (const float*)d_in[0];
    const float* b0   = (const float*)d_in[1];
    const float* b1   = (const float*)d_in[2];
    const float* b2   = (const float*)d_in[3];
    const float* W    = (const float*)d_in[4];
    const float* bias = (const float*)d_in[5];
    float* y = (float*)d_out;

    int hop_smem = 168960;
    cudaFuncSetAttribute(hop_kernel, cudaFuncAttributeMaxDynamicSharedMemorySize, hop_smem);
    cudaFuncSetAttribute(mix_kernel, cudaFuncAttributeMaxDynamicSharedMemorySize,
                         (224 * WPAD + 16 * C_) * 4);

    transpose_kernel<<<dim3(C_ / 32, M_ / 32, B_ * F_), dim3(32, 8)>>>(x);
    hop_kernel<<<PAIRS * 3, 512, hop_smem>>>(b0, b1, b2);
    mix_kernel<<<PAIRS, 256, (224 * WPAD + 16 * C_) * 4>>>(W, bias, y);
}

// round 11
// speedup vs baseline: 2.8999x; 1.3400x over previous
#include <cuda_runtime.h>
#include <cuda_bf16.h>
#include <cuda_fp16.h>
#include <cstdint>

// x: [8,32,256,64] f32 | baseK: [8,64,256,256] f32 | W: [64,224] | b: [64] | y: [8,64,256,64]
#define B_   8
#define F_   32
#define C_   256
#define M_   64
#define CO_  64
#define PAIRS 512
#define KC   64              // A chunk rows (hop0 pipeline)
#define NCHUNK 4             // 256/KC
#define LDA  264             // padded row stride (halves)

__device__ __half g_scratch_h[6 * PAIRS * F_ * C_];   // hop results, fp16
__device__ __half g_xTh[PAIRS * F_ * C_];             // fp16(x) transposed
__device__ __half g_xT_lo[PAIRS * F_ * C_];           // fp16 residual of x

// ---------------- helpers ----------------
__device__ __forceinline__ uint32_t smem_u32(const void* p) {
    uint32_t a;
    asm("{ .reg .u64 t; cvta.to.shared.u64 t, %1; cvt.u32.u64 %0, t; }" : "=r"(a) : "l"(p));
    return a;
}
__device__ __forceinline__ uint32_t pack_h2(float x, float y) {
    uint32_t r;
    asm("cvt.rn.f16x2.f32 %0, %1, %2;" : "=r"(r) : "f"(y), "f"(x));
    return r;
}
__device__ __forceinline__ void split2h(float x, float y, uint32_t& hi, uint32_t& lo) {
    hi = pack_h2(x, y);
    float hx, hy;
    asm("{ .reg .f16 a,b; mov.b32 {a,b}, %2; cvt.f32.f16 %0, a; cvt.f32.f16 %1, b; }"
        : "=f"(hx), "=f"(hy) : "r"(hi));
    lo = pack_h2(x - hx, y - hy);
}
__device__ __forceinline__ void ldm_x4(uint32_t* r, uint32_t addr) {
    asm volatile("ldmatrix.sync.aligned.m8n8.x4.shared.b16 {%0,%1,%2,%3}, [%4];"
                 : "=r"(r[0]), "=r"(r[1]), "=r"(r[2]), "=r"(r[3]) : "r"(addr));
}
__device__ __forceinline__ void ldm_x4t(uint32_t* r, uint32_t addr) {
    asm volatile("ldmatrix.sync.aligned.m8n8.x4.trans.shared.b16 {%0,%1,%2,%3}, [%4];"
                 : "=r"(r[0]), "=r"(r[1]), "=r"(r[2]), "=r"(r[3]) : "r"(addr));
}
__device__ __forceinline__ void mma_f16(float* d, const uint32_t* a, const uint32_t* b) {
    asm volatile("mma.sync.aligned.m16n8k16.row.col.f32.f16.f16.f32 "
                 "{%0,%1,%2,%3}, {%4,%5,%6,%7}, {%8,%9}, {%0,%1,%2,%3};"
                 : "+f"(d[0]), "+f"(d[1]), "+f"(d[2]), "+f"(d[3])
                 : "r"(a[0]), "r"(a[1]), "r"(a[2]), "r"(a[3]), "r"(b[0]), "r"(b[1]));
}

// ---------------- kernel 0: transpose x -> xTh (fp16 hi) + xT_lo (fp16 residual) ----------------
__global__ void transpose_kernel(const float* __restrict__ x) {
    __shared__ float tile[32][33];
    int bf = blockIdx.z;
    int bb = bf >> 5, f = bf & 31;
    int n0 = blockIdx.x * 32, m0 = blockIdx.y * 32;
    int tx = threadIdx.x, ty = threadIdx.y;
    const float* src = x + (size_t)bf * (C_ * M_);
#pragma unroll
    for (int r = 0; r < 32; r += 8)
        tile[ty + r][tx] = src[(size_t)(n0 + ty + r) * M_ + m0 + tx];
    __syncthreads();
#pragma unroll
    for (int r = 0; r < 32; r += 8) {
        int m = m0 + ty + r, n = n0 + tx;
        float v = tile[tx][ty + r];
        __half h = __float2half_rn(v);
        __half lo = __float2half_rn(v - __half2float(h));
        size_t idx = ((size_t)(bb * M_ + m) * F_ + f) * C_ + n;
        g_xTh[idx] = h;
        g_xT_lo[idx] = lo;
    }
}

// ---------------- kernel 1: HMMA hop GEMMs, single fp16, persistent A ----------------
__global__ __launch_bounds__(512, 1)
void hop_kernel(const float* __restrict__ b0,
                const float* __restrict__ b1,
                const float* __restrict__ b2) {
    extern __shared__ __align__(16) uint16_t sm[];
    uint16_t* As   = sm;            // 256*LDA
    uint16_t* Xs   = sm + 67584;    // 32*LDA
    uint16_t* StgH = sm + 76032;    // 32*LDA

    int bx = blockIdx.x;
    int base = bx % 3;
    int pair = bx / 3;
    const float* A = (base == 0 ? b0 : base == 1 ? b1 : b2) + (size_t)pair * (C_ * C_);

    int t = threadIdx.x;
    int w = t >> 5;
    int l = t & 31;
    int g = l >> 2;
    int tig = l & 3;
    int mrow  = (w >> 3) * 16;
    int vbase = (w & 7) * 32;

    uint32_t xs_b = smem_u32(Xs);
    uint32_t as_b = smem_u32(As);

    int lrow = l & 15;
    int lhalf = (l >> 4) & 1;
    uint32_t x_off = (uint32_t)((mrow + lrow) * LDA + lhalf * 8) * 2;
    uint32_t b_off = (uint32_t)(lrow * LDA + vbase + lhalf * 8) * 2;

    // ---- initial X -> Xs (already fp16 in gmem) ----
    {
        const uint4* xsrc = (const uint4*)(g_xTh + (size_t)pair * (F_ * C_));
#pragma unroll
        for (int r = 0; r < 2; ++r) {
            int i = t + 512 * r;              // 1024 uint4
            int f = i >> 5, q = i & 31;
            *(uint4*)&Xs[f * LDA + q * 8] = xsrc[i];
        }
    }

    const float4* A4 = (const float4*)A;
    float acc[4][4];

    // ================= hop 0 =================
#pragma unroll
    for (int j = 0; j < 4; ++j)
#pragma unroll
        for (int q = 0; q < 4; ++q) acc[j][q] = 0.f;

    float4 ldg[8];
#pragma unroll
    for (int r = 0; r < 8; ++r) ldg[r] = A4[t + 512 * r];
#pragma unroll
    for (int r = 0; r < 8; ++r) {
        int i = t + 512 * r;
        int nloc = i >> 6, q = i & 63;
        uint32_t p0 = pack_h2(ldg[r].x, ldg[r].y);
        uint32_t p1 = pack_h2(ldg[r].z, ldg[r].w);
        *(uint2*)&As[nloc * LDA + q * 4] = make_uint2(p0, p1);
    }
    __syncthreads();

    for (int c = 0; c < NCHUNK; ++c) {
        if (c + 1 < NCHUNK) {
#pragma unroll
            for (int r = 0; r < 8; ++r)
                ldg[r] = A4[(c + 1) * 4096 + t + 512 * r];
        }
#pragma unroll
        for (int ks = 0; ks < 4; ++ks) {
            int k = c * KC + ks * 16;
            uint32_t xh[4];
            ldm_x4(xh, xs_b + x_off + (uint32_t)k * 2);
            uint32_t rofs = b_off + (uint32_t)(k * LDA) * 2;
#pragma unroll
            for (int jj = 0; jj < 2; ++jj) {
                uint32_t bb4[4];
                ldm_x4t(bb4, as_b + rofs + jj * 32);
                mma_f16(acc[2 * jj],     xh, bb4);
                mma_f16(acc[2 * jj + 1], xh, bb4 + 2);
            }
        }
        if (c + 1 < NCHUNK) {
            int rb = (c + 1) * KC;
#pragma unroll
            for (int r = 0; r < 8; ++r) {
                int i = t + 512 * r;
                int nloc = i >> 6, q = i & 63;
                uint32_t p0 = pack_h2(ldg[r].x, ldg[r].y);
                uint32_t p1 = pack_h2(ldg[r].z, ldg[r].w);
                *(uint2*)&As[(rb + nloc) * LDA + q * 4] = make_uint2(p0, p1);
            }
        }
        __syncthreads();
    }

#pragma unroll
    for (int j = 0; j < 4; ++j) {
        int col = vbase + 8 * j + 2 * tig;
        int r0 = mrow + g, r1 = mrow + g + 8;
        uint32_t p0 = pack_h2(acc[j][0], acc[j][1]);
        uint32_t p1 = pack_h2(acc[j][2], acc[j][3]);
        *(uint32_t*)&StgH[r0 * LDA + col] = p0;
        *(uint32_t*)&StgH[r1 * LDA + col] = p1;
        *(uint32_t*)&Xs[r0 * LDA + col] = p0;
        *(uint32_t*)&Xs[r1 * LDA + col] = p1;
    }
    __syncthreads();
    {
        __half* scr = g_scratch_h + ((size_t)(base * 2 + 0) * PAIRS + pair) * (F_ * C_);
#pragma unroll
        for (int r = 0; r < 2; ++r) {
            int i = t + 512 * r;
            int f = i >> 5, q = i & 31;
            ((uint4*)scr)[i] = *(const uint4*)&StgH[f * LDA + q * 8];
        }
    }
    __syncthreads();

    // ================= hop 1 =================
#pragma unroll
    for (int j = 0; j < 4; ++j)
#pragma unroll
        for (int q = 0; q < 4; ++q) acc[j][q] = 0.f;

#pragma unroll 4
    for (int ks = 0; ks < 16; ++ks) {
        int k = ks * 16;
        uint32_t xh[4];
        ldm_x4(xh, xs_b + x_off + (uint32_t)k * 2);
        uint32_t rofs = b_off + (uint32_t)(k * LDA) * 2;
#pragma unroll
        for (int jj = 0; jj < 2; ++jj) {
            uint32_t bb4[4];
            ldm_x4t(bb4, as_b + rofs + jj * 32);
            mma_f16(acc[2 * jj],     xh, bb4);
            mma_f16(acc[2 * jj + 1], xh, bb4 + 2);
        }
    }
#pragma unroll
    for (int j = 0; j < 4; ++j) {
        int col = vbase + 8 * j + 2 * tig;
        int r0 = mrow + g, r1 = mrow + g + 8;
        *(uint32_t*)&StgH[r0 * LDA + col] = pack_h2(acc[j][0], acc[j][1]);
        *(uint32_t*)&StgH[r1 * LDA + col] = pack_h2(acc[j][2], acc[j][3]);
    }
    __syncthreads();
    {
        __half* scr = g_scratch_h + ((size_t)(base * 2 + 1) * PAIRS + pair) * (F_ * C_);
#pragma unroll
        for (int r = 0; r < 2; ++r) {
            int i = t + 512 * r;
            int f = i >> 5, q = i & 31;
            ((uint4*)scr)[i] = *(const uint4*)&StgH[f * LDA + q * 8];
        }
    }
}

// ---------------- kernel 2: channel mix on HMMA ----------------
// D[64,256] = (Whi+Wlo)[64,224] @ Hhi[224,256] + Whi @ Hlo(x ftiles only)
// smem (halves): Whi [64][264] @0, Wlo @16896, Htiles[4][16][264] @33792
//   Htile 0,1: Hhi double buffer; 2,3: Hlo for ftile 0,1
// 8 warps: w>>1 = o-tile (16 rows), w&1 = v-half (128 cols). occ 2.
#define LDW 264
#define MIX_SMEM ((16896 * 2 + 4 * 16 * 264) * 2)
__global__ __launch_bounds__(256, 2)
void mix_kernel(const float* __restrict__ W,
                const float* __restrict__ bias,
                float* __restrict__ y) {
    extern __shared__ __align__(16) uint16_t ms[];
    uint16_t* Whi = ms;
    uint16_t* Wlo = ms + 16896;
    uint16_t* Ht  = ms + 33792;   // 4 tiles of 16*264

    int pair = blockIdx.x;
    int bb = pair >> 6, m = pair & 63;
    int t = threadIdx.x;
    int w = t >> 5;
    int l = t & 31;
    int g = l >> 2;
    int tig = l & 3;
    int ot = (w >> 1) * 16;      // o-tile base
    int vh = (w & 1) * 128;      // v-half base

    uint32_t whi_b = smem_u32(Whi);
    uint32_t wlo_b = smem_u32(Wlo);
    uint32_t ht_b  = smem_u32(Ht);

    int lrow = l & 15;
    int lhalf = (l >> 4) & 1;
    uint32_t w_off = (uint32_t)((ot + lrow) * LDW + lhalf * 8) * 2;
    uint32_t h_off = (uint32_t)(lrow * LDW + vh + lhalf * 8) * 2;

    // ---- W load + split ----
    {
        const float2* W2 = (const float2*)W;   // 7168 float2
        for (int i = t; i < 7168; i += 256) {
            int o = i / 112, kk = i % 112;     // kk = f/2
            float2 wv = W2[i];
            uint32_t hi, lo;
            split2h(wv.x, wv.y, hi, lo);
            ((uint32_t*)Whi)[o * (LDW / 2) + kk] = hi;
            ((uint32_t*)Wlo)[o * (LDW / 2) + kk] = lo;
        }
    }
    // ---- preload Hhi ftile0 -> tile0; Hlo ftile0,1 -> tiles 2,3 ----
    {
        const uint4* s0 = (const uint4*)(g_xTh + (size_t)pair * (F_ * C_));
        const uint4* sl = (const uint4*)(g_xT_lo + (size_t)pair * (F_ * C_));
#pragma unroll
        for (int r = 0; r < 2; ++r) {
            int i = t + 256 * r;               // 512 uint4 per tile
            int f = i >> 5, q = i & 31;
            *(uint4*)&Ht[0 * 4224 + f * LDW + q * 8] = s0[i];          // Hhi ft0
            *(uint4*)&Ht[2 * 4224 + f * LDW + q * 8] = sl[i];          // Hlo ft0
            *(uint4*)&Ht[3 * 4224 + f * LDW + q * 8] = sl[i + 512];    // Hlo ft1
        }
    }
    __syncthreads();

    float acc[16][4];
#pragma unroll
    for (int j = 0; j < 16; ++j)
#pragma unroll
        for (int q = 0; q < 4; ++q) acc[j][q] = 0.f;

    uint4 ldgbuf[2];
    for (int ft = 0; ft < 14; ++ft) {
        int cur = ft & 1;
        if (ft + 1 < 14) {
            int nf = ft + 1;
            const uint4* src;
            if (nf < 2) {
                src = (const uint4*)(g_xTh + (size_t)pair * (F_ * C_) + nf * 16 * C_);
            } else {
                int blk = (nf - 2) >> 1;
                int fr  = ((nf - 2) & 1) * 16;
                src = (const uint4*)(g_scratch_h + ((size_t)blk * PAIRS + pair) * (F_ * C_) + fr * C_);
            }
            ldgbuf[0] = src[t];
            ldgbuf[1] = src[t + 256];
        }
        // MMA on tile[cur]
        uint32_t whi4[4], wlo4[4];
        ldm_x4(whi4, whi_b + w_off + (uint32_t)ft * 32);
        ldm_x4(wlo4, wlo_b + w_off + (uint32_t)ft * 32);
        uint32_t hb = ht_b + (uint32_t)cur * 4224 * 2;
#pragma unroll
        for (int jj = 0; jj < 8; ++jj) {
            uint32_t b4[4];
            ldm_x4t(b4, hb + h_off + jj * 32);
            mma_f16(acc[2 * jj],     whi4, b4);
            mma_f16(acc[2 * jj],     wlo4, b4);
            mma_f16(acc[2 * jj + 1], whi4, b4 + 2);
            mma_f16(acc[2 * jj + 1], wlo4, b4 + 2);
        }
        if (ft < 2) {   // x-ftile residual: Whi * Hlo
            uint32_t hlb = ht_b + (uint32_t)(2 + ft) * 4224 * 2;
#pragma unroll
            for (int jj = 0; jj < 8; ++jj) {
                uint32_t b4[4];
                ldm_x4t(b4, hlb + h_off + jj * 32);
                mma_f16(acc[2 * jj],     whi4, b4);
                mma_f16(acc[2 * jj + 1], whi4, b4 + 2);
            }
        }
        __syncthreads();
        if (ft + 1 < 14) {
            int nxt = cur ^ 1;
#pragma unroll
            for (int r = 0; r < 2; ++r) {
                int i = t + 256 * r;
                int f = i >> 5, q = i & 31;
                *(uint4*)&Ht[nxt * 4224 + f * LDW + q * 8] = ldgbuf[r];
            }
        }
        __syncthreads();
    }

    // epilogue: y + bias (scalar strided stores, L2-merged)
#pragma unroll
    for (int j = 0; j < 16; ++j) {
        int col = vh + (j >> 1) * 16 + (j & 1) * 8 + 2 * tig;
        int r0 = ot + g, r1 = ot + g + 8;
        float bv0 = __ldg(&bias[r0]);
        float bv1 = __ldg(&bias[r1]);
        size_t base0 = ((size_t)(bb * CO_ + r0) * C_ + col) * M_ + m;
        size_t base1 = ((size_t)(bb * CO_ + r1) * C_ + col) * M_ + m;
        y[base0]      = acc[j][0] + bv0;
        y[base0 + M_] = acc[j][1] + bv0;
        y[base1]      = acc[j][2] + bv1;
        y[base1 + M_] = acc[j][3] + bv1;
    }
}

extern "C" void kernel_launch(void* const* d_in, const int* in_sizes, int n_in,
                              void* d_out, int out_size) {
    const float* x    = (const float*)d_in[0];
    const float* b0   = (const float*)d_in[1];
    const float* b1   = (const float*)d_in[2];
    const float* b2   = (const float*)d_in[3];
    const float* W    = (const float*)d_in[4];
    const float* bias = (const float*)d_in[5];
    float* y = (float*)d_out;

    int hop_smem = 168960;
    cudaFuncSetAttribute(hop_kernel, cudaFuncAttributeMaxDynamicSharedMemorySize, hop_smem);
    cudaFuncSetAttribute(mix_kernel, cudaFuncAttributeMaxDynamicSharedMemorySize, MIX_SMEM);

    transpose_kernel<<<dim3(C_ / 32, M_ / 32, B_ * F_), dim3(32, 8)>>>(x);
    hop_kernel<<<PAIRS * 3, 512, hop_smem>>>(b0, b1, b2);
    mix_kernel<<<PAIRS, 256, MIX_SMEM>>>(W, bias, y);
}